// round 2
// baseline (speedup 1.0000x reference)
#include <cuda_runtime.h>
#include <math.h>
#include <stdint.h>

// Problem dims
#define B_   2
#define S_   2048
#define D_   1024
#define H_   16
#define DK_  64
#define F_   4096
#define E_   8
#define TOK  (B_*S_)              // 4096 tokens
#define CAP_ROWS (TOK*2 + E_*128) // 9216 padded gather capacity

// GEMM tiling
#define BM 64
#define BN 64
#define BK 16

// ---------------- scratch (device globals; no allocation) ----------------
__device__ __align__(128) float g_x2[TOK*D_];
__device__ __align__(128) float g_q [TOK*D_];
__device__ __align__(128) float g_k [TOK*D_];
__device__ __align__(128) float g_v [TOK*D_];
__device__ __align__(128) float g_attn[TOK*D_];
__device__ __align__(128) float g_kvp[32*8*DK_*DK_];
__device__ __align__(128) float g_kv [32*DK_*DK_];
__device__ __align__(128) float g_ksp[32*8*DK_];
__device__ __align__(128) float g_ks [32*DK_];
__device__ __align__(128) float g_xg[(size_t)CAP_ROWS*D_];
__device__ __align__(128) float g_h [(size_t)CAP_ROWS*F_];
__device__ __align__(128) float g_y [(size_t)CAP_ROWS*D_];
__device__ int   g_cnt[E_];
__device__ int   g_off[E_+1];
__device__ int   g_cur[E_];
__device__ int   g_topi[TOK*2];
__device__ float g_topw[TOK*2];
__device__ int   g_row[TOK*2];

// ---------------- helpers ----------------
__device__ __forceinline__ float silu_gate(float a, float c) {
    return a / (1.f + expf(-a)) * c;
}
__device__ __forceinline__ float phi1(float x) {   // elu(x)+1
    return x > 0.f ? x + 1.f : expf(x);
}

#define FMA16(ACC, a, bv) do { \
    ACC[0][0] += a.x*bv.x; ACC[0][1] += a.x*bv.y; ACC[0][2] += a.x*bv.z; ACC[0][3] += a.x*bv.w; \
    ACC[1][0] += a.y*bv.x; ACC[1][1] += a.y*bv.y; ACC[1][2] += a.y*bv.z; ACC[1][3] += a.y*bv.w; \
    ACC[2][0] += a.z*bv.x; ACC[2][1] += a.z*bv.y; ACC[2][2] += a.z*bv.z; ACC[2][3] += a.z*bv.w; \
    ACC[3][0] += a.w*bv.x; ACC[3][1] += a.w*bv.y; ACC[3][2] += a.w*bv.z; ACC[3][3] += a.w*bv.w; \
} while (0)

// Shared GEMM tile loop. A: row-major [.. x lda], already offset to block row.
// W0/W1: row-major [K x ldw], already offset to block col. 256 threads.
template<int NW>
__device__ __forceinline__ void gemm_body(
    const float* __restrict__ A, int lda,
    const float* __restrict__ W0, const float* __restrict__ W1,
    int ldw, int K,
    float (&acc0)[4][4], float (&acc1)[4][4])
{
    __shared__ float As[BK*BM];
    __shared__ float Ws[NW][BK*BN];
    const int tid = threadIdx.x;
    const int tx = tid & 15, ty = tid >> 4;
    const int ar = tid >> 2;            // 0..63
    const int ac = (tid & 3) << 2;      // 0,4,8,12
    const int wr = tid >> 4;            // 0..15
    const int wc = (tid & 15) << 2;     // 0..60

    for (int k0 = 0; k0 < K; k0 += BK) {
        float4 av = *(const float4*)(A + (size_t)ar*lda + k0 + ac);
        As[(ac+0)*BM + ar] = av.x;
        As[(ac+1)*BM + ar] = av.y;
        As[(ac+2)*BM + ar] = av.z;
        As[(ac+3)*BM + ar] = av.w;
        *(float4*)(&Ws[0][wr*BN + wc]) = *(const float4*)(W0 + (size_t)(k0+wr)*ldw + wc);
        if (NW == 2)
            *(float4*)(&Ws[1][wr*BN + wc]) = *(const float4*)(W1 + (size_t)(k0+wr)*ldw + wc);
        __syncthreads();
        #pragma unroll
        for (int kk = 0; kk < BK; kk++) {
            float4 a  = *(const float4*)(&As[kk*BM + ty*4]);
            float4 b0 = *(const float4*)(&Ws[0][kk*BN + tx*4]);
            FMA16(acc0, a, b0);
            if (NW == 2) {
                float4 b1 = *(const float4*)(&Ws[1][kk*BN + tx*4]);
                FMA16(acc1, a, b1);
            }
        }
        __syncthreads();
    }
}

// ---------------- kernels ----------------

// LayerNorm over D, block per token, writes g_x2
__global__ void __launch_bounds__(256) ln_kernel(
    const float* __restrict__ x, const float* __restrict__ g, const float* __restrict__ b)
{
    __shared__ float rs[256], rq[256];
    const int t = blockIdx.x, tid = threadIdx.x;
    float4 v = ((const float4*)(x + (size_t)t*D_))[tid];
    rs[tid] = v.x + v.y + v.z + v.w;
    rq[tid] = v.x*v.x + v.y*v.y + v.z*v.z + v.w*v.w;
    __syncthreads();
    for (int o = 128; o > 0; o >>= 1) {
        if (tid < o) { rs[tid] += rs[tid+o]; rq[tid] += rq[tid+o]; }
        __syncthreads();
    }
    float mean = rs[0] * (1.f/D_);
    float var  = rq[0] * (1.f/D_) - mean*mean;
    float inv  = rsqrtf(var + 1e-5f);
    float4 gg = ((const float4*)g)[tid];
    float4 bb = ((const float4*)b)[tid];
    float4 o4;
    o4.x = (v.x - mean)*inv*gg.x + bb.x;
    o4.y = (v.y - mean)*inv*gg.y + bb.y;
    o4.z = (v.z - mean)*inv*gg.z + bb.z;
    o4.w = (v.w - mean)*inv*gg.w + bb.w;
    ((float4*)(g_x2 + (size_t)t*D_))[tid] = o4;
}

// Gated projection: C = maybe_phi( silu(x2@W1+b1) * (x2@W2+b2) ), dst: 0=q 1=k 2=v
__global__ void __launch_bounds__(256) gated_proj_kernel(
    const float* __restrict__ W1, const float* __restrict__ b1,
    const float* __restrict__ W2, const float* __restrict__ b2,
    int dst, int applyPhi)
{
    const int bm0 = blockIdx.x * BM, bn0 = blockIdx.y * BN;
    float acc0[4][4] = {}, acc1[4][4] = {};
    gemm_body<2>(g_x2 + (size_t)bm0*D_, D_, W1 + bn0, W2 + bn0, D_, D_, acc0, acc1);
    float* C = (dst == 0) ? g_q : (dst == 1) ? g_k : g_v;
    const int tx = threadIdx.x & 15, ty = threadIdx.x >> 4;
    const int n0 = bn0 + tx*4;
    float4 bb1 = *(const float4*)(b1 + n0);
    float4 bb2 = *(const float4*)(b2 + n0);
    #pragma unroll
    for (int i = 0; i < 4; i++) {
        int m = bm0 + ty*4 + i;
        float4 o;
        o.x = silu_gate(acc0[i][0] + bb1.x, acc1[i][0] + bb2.x);
        o.y = silu_gate(acc0[i][1] + bb1.y, acc1[i][1] + bb2.y);
        o.z = silu_gate(acc0[i][2] + bb1.z, acc1[i][2] + bb2.z);
        o.w = silu_gate(acc0[i][3] + bb1.w, acc1[i][3] + bb2.w);
        if (applyPhi) { o.x = phi1(o.x); o.y = phi1(o.y); o.z = phi1(o.z); o.w = phi1(o.w); }
        *(float4*)(C + (size_t)m*D_ + n0) = o;
    }
}

// Partial kv outer-product accumulation per (b,h,chunk of 256 s)
__global__ void __launch_bounds__(256) kv_partial_kernel()
{
    __shared__ float pk[DK_], pv[DK_];
    const int bh = blockIdx.x, c = blockIdx.y;
    const int b = bh >> 4, h = bh & 15;
    const int tid = threadIdx.x;
    const int d = tid >> 2, eg = tid & 3;
    float acc[16];
    #pragma unroll
    for (int j = 0; j < 16; j++) acc[j] = 0.f;
    float ks = 0.f;
    for (int s = c*256; s < c*256 + 256; s++) {
        size_t base = ((size_t)(b*S_ + s))*D_ + h*DK_;
        if (tid < 64)        pk[tid]      = g_k[base + tid];
        else if (tid < 128)  pv[tid - 64] = g_v[base + tid - 64];
        __syncthreads();
        float kd = pk[d];
        #pragma unroll
        for (int j = 0; j < 16; j++) acc[j] += kd * pv[eg + 4*j];
        if (eg == 0) ks += kd;
        __syncthreads();
    }
    size_t ob = ((size_t)(bh*8 + c))*DK_*DK_;
    #pragma unroll
    for (int j = 0; j < 16; j++) g_kvp[ob + d*DK_ + eg + 4*j] = acc[j];
    if (eg == 0) g_ksp[(bh*8 + c)*DK_ + d] = ks;
}

__global__ void kv_reduce_kernel()
{
    int i = blockIdx.x*256 + threadIdx.x;
    if (i < 32*DK_*DK_) {
        int bh = i >> 12, r = i & 4095;
        float s = 0.f;
        #pragma unroll
        for (int c = 0; c < 8; c++) s += g_kvp[((size_t)(bh*8 + c))*4096 + r];
        g_kv[i] = s;
    }
    int j = i - 32*DK_*DK_;
    if (j >= 0 && j < 32*DK_) {
        int bh = j >> 6, d = j & 63;
        float s = 0.f;
        #pragma unroll
        for (int c = 0; c < 8; c++) s += g_ksp[(bh*8 + c)*DK_ + d];
        g_ks[j] = s;
    }
}

// num/den: out = (phi_q @ kv) / (phi_q . ksum + eps)
__global__ void __launch_bounds__(256) attn_apply_kernel()
{
    __shared__ float kvs[DK_*DK_];
    __shared__ float kss[DK_];
    __shared__ float qs[4*DK_];
    const int bh = blockIdx.x;
    const int b = bh >> 4, h = bh & 15;
    const int tid = threadIdx.x;
    for (int i = tid; i < DK_*DK_; i += 256) kvs[i] = g_kv[(size_t)bh*DK_*DK_ + i];
    if (tid < DK_) kss[tid] = g_ks[bh*DK_ + tid];
    __syncthreads();
    const int sl = tid >> 6, e = tid & 63;
    const int sbase = blockIdx.y * 64;
    for (int pass = 0; pass < 16; pass++) {
        int s = sbase + pass*4 + sl;
        qs[tid] = g_q[((size_t)(b*S_ + s))*D_ + h*DK_ + e];
        __syncthreads();
        float acc = 0.f, qk = 0.f;
        #pragma unroll
        for (int d = 0; d < DK_; d++) {
            float qd = qs[sl*DK_ + d];
            acc += qd * kvs[d*DK_ + e];
            qk  += qd * kss[d];
        }
        g_attn[((size_t)(b*S_ + s))*D_ + h*DK_ + e] = acc / (qk + 1e-6f);
        __syncthreads();
    }
}

// out = attn @ wo + bo + residual x  (writes full d_out)
__global__ void __launch_bounds__(256) out_proj_kernel(
    const float* __restrict__ W, const float* __restrict__ bias,
    const float* __restrict__ res, float* __restrict__ C)
{
    const int bm0 = blockIdx.x * BM, bn0 = blockIdx.y * BN;
    float acc0[4][4] = {}, accd[4][4] = {};
    gemm_body<1>(g_attn + (size_t)bm0*D_, D_, W + bn0, (const float*)0, D_, D_, acc0, accd);
    const int tx = threadIdx.x & 15, ty = threadIdx.x >> 4;
    const int n0 = bn0 + tx*4;
    float4 bb = *(const float4*)(bias + n0);
    #pragma unroll
    for (int i = 0; i < 4; i++) {
        int m = bm0 + ty*4 + i;
        float4 rr = *(const float4*)(res + (size_t)m*D_ + n0);
        float4 o;
        o.x = acc0[i][0] + bb.x + rr.x;
        o.y = acc0[i][1] + bb.y + rr.y;
        o.z = acc0[i][2] + bb.z + rr.z;
        o.w = acc0[i][3] + bb.w + rr.w;
        *(float4*)(C + (size_t)m*D_ + n0) = o;
    }
}

__global__ void zero_cnt_kernel() { if (threadIdx.x < E_) g_cnt[threadIdx.x] = 0; }

__global__ void zero_xg_kernel()
{
    size_t i = ((size_t)blockIdx.x*256 + threadIdx.x)*4;
    *(float4*)(g_xg + i) = make_float4(0.f, 0.f, 0.f, 0.f);
}

// gate logits + softmax + top2 ; one warp per token
__global__ void __launch_bounds__(256) routing_kernel(
    const float* __restrict__ gw, const float* __restrict__ gb)
{
    const int lane = threadIdx.x & 31;
    const int warp = threadIdx.x >> 5;
    const int t = blockIdx.x*8 + warp;
    const float* xr = g_x2 + (size_t)t*D_;
    float lg[8];
    #pragma unroll
    for (int e = 0; e < 8; e++) lg[e] = 0.f;
    for (int d = lane; d < D_; d += 32) {
        float xv = xr[d];
        const float4* wr = (const float4*)(gw + (size_t)d*8);
        float4 w0 = wr[0], w1 = wr[1];
        lg[0] += xv*w0.x; lg[1] += xv*w0.y; lg[2] += xv*w0.z; lg[3] += xv*w0.w;
        lg[4] += xv*w1.x; lg[5] += xv*w1.y; lg[6] += xv*w1.z; lg[7] += xv*w1.w;
    }
    #pragma unroll
    for (int o = 16; o > 0; o >>= 1) {
        #pragma unroll
        for (int e = 0; e < 8; e++) lg[e] += __shfl_xor_sync(0xffffffffu, lg[e], o);
    }
    if (lane == 0) {
        float p[8], mx = -1e30f;
        #pragma unroll
        for (int e = 0; e < 8; e++) { lg[e] += gb[e]; mx = fmaxf(mx, lg[e]); }
        float se = 0.f;
        #pragma unroll
        for (int e = 0; e < 8; e++) { p[e] = expf(lg[e] - mx); se += p[e]; }
        int i0 = 0;
        #pragma unroll
        for (int e = 1; e < 8; e++) if (p[e] > p[i0]) i0 = e;
        int i1 = (i0 == 0) ? 1 : 0;
        #pragma unroll
        for (int e = 0; e < 8; e++) if (e != i0 && p[e] > p[i1]) i1 = e;
        float v0 = p[i0]/se, v1 = p[i1]/se;
        float inv = 1.f / (v0 + v1 + 1e-6f);
        g_topi[t*2]   = i0; g_topi[t*2+1] = i1;
        g_topw[t*2]   = v0*inv; g_topw[t*2+1] = v1*inv;
        atomicAdd(&g_cnt[i0], 1);
        atomicAdd(&g_cnt[i1], 1);
    }
}

__global__ void offsets_kernel()
{
    if (threadIdx.x == 0) {
        int o = 0;
        for (int e = 0; e < E_; e++) {
            g_off[e] = o;
            o += (g_cnt[e] + 127) & ~127;
            g_cur[e] = 0;
        }
        g_off[E_] = o;
    }
}

// assign a row per (token,slot) and copy x2 row into gather buffer
__global__ void __launch_bounds__(256) place_gather_kernel()
{
    const int slot = blockIdx.x;
    const int t = slot >> 1;
    __shared__ int row_s;
    if (threadIdx.x == 0) {
        int e = g_topi[slot];
        int pos = atomicAdd(&g_cur[e], 1);
        int row = g_off[e] + pos;
        g_row[slot] = row;
        row_s = row;
    }
    __syncthreads();
    int row = row_s;
    float4* dst = (float4*)(g_xg + (size_t)row*D_);
    const float4* src = (const float4*)(g_x2 + (size_t)t*D_);
    dst[threadIdx.x] = src[threadIdx.x];
}

// h = silu(xg@w1[e]+b1[e]) * (xg@w3[e]+b3[e])
__global__ void __launch_bounds__(256) moe_h_kernel(
    const float* __restrict__ ew1, const float* __restrict__ eb1,
    const float* __restrict__ ew3, const float* __restrict__ eb3)
{
    const int bm0 = blockIdx.x * BM;
    if (bm0 >= g_off[E_]) return;
    int e = 0;
    #pragma unroll
    for (int i = 0; i < E_; i++) if (bm0 >= g_off[i+1]) e = i + 1;
    const int bn0 = blockIdx.y * BN;
    float acc0[4][4] = {}, acc1[4][4] = {};
    gemm_body<2>(g_xg + (size_t)bm0*D_, D_,
                 ew1 + (size_t)e*D_*F_ + bn0,
                 ew3 + (size_t)e*D_*F_ + bn0, F_, D_, acc0, acc1);
    const int tx = threadIdx.x & 15, ty = threadIdx.x >> 4;
    const int n0 = bn0 + tx*4;
    float4 bb1 = *(const float4*)(eb1 + (size_t)e*F_ + n0);
    float4 bb3 = *(const float4*)(eb3 + (size_t)e*F_ + n0);
    #pragma unroll
    for (int i = 0; i < 4; i++) {
        int m = bm0 + ty*4 + i;
        float4 o;
        o.x = silu_gate(acc0[i][0] + bb1.x, acc1[i][0] + bb3.x);
        o.y = silu_gate(acc0[i][1] + bb1.y, acc1[i][1] + bb3.y);
        o.z = silu_gate(acc0[i][2] + bb1.z, acc1[i][2] + bb3.z);
        o.w = silu_gate(acc0[i][3] + bb1.w, acc1[i][3] + bb3.w);
        *(float4*)(g_h + (size_t)m*F_ + n0) = o;
    }
}

// y = h @ w2[e] + b2[e]
__global__ void __launch_bounds__(256) moe_y_kernel(
    const float* __restrict__ ew2, const float* __restrict__ eb2)
{
    const int bm0 = blockIdx.x * BM;
    if (bm0 >= g_off[E_]) return;
    int e = 0;
    #pragma unroll
    for (int i = 0; i < E_; i++) if (bm0 >= g_off[i+1]) e = i + 1;
    const int bn0 = blockIdx.y * BN;
    float acc0[4][4] = {}, accd[4][4] = {};
    gemm_body<1>(g_h + (size_t)bm0*F_, F_,
                 ew2 + (size_t)e*F_*D_ + bn0, (const float*)0, D_, F_, acc0, accd);
    const int tx = threadIdx.x & 15, ty = threadIdx.x >> 4;
    const int n0 = bn0 + tx*4;
    float4 bb = *(const float4*)(eb2 + (size_t)e*D_ + n0);
    #pragma unroll
    for (int i = 0; i < 4; i++) {
        int m = bm0 + ty*4 + i;
        float4 o;
        o.x = acc0[i][0] + bb.x;
        o.y = acc0[i][1] + bb.y;
        o.z = acc0[i][2] + bb.z;
        o.w = acc0[i][3] + bb.w;
        *(float4*)(g_y + (size_t)m*D_ + n0) = o;
    }
}

// out[t] += w0*y[row0] + w1*y[row1]
__global__ void __launch_bounds__(256) combine_kernel(float* __restrict__ out)
{
    const int t = blockIdx.x;
    const int r0 = g_row[2*t], r1 = g_row[2*t+1];
    const float w0 = g_topw[2*t], w1 = g_topw[2*t+1];
    const int c = threadIdx.x;
    float4 o  = ((float4*)(out + (size_t)t*D_))[c];
    float4 y0 = ((const float4*)(g_y + (size_t)r0*D_))[c];
    float4 y1 = ((const float4*)(g_y + (size_t)r1*D_))[c];
    o.x += w0*y0.x + w1*y1.x;
    o.y += w0*y0.y + w1*y1.y;
    o.z += w0*y0.z + w1*y1.z;
    o.w += w0*y0.w + w1*y1.w;
    ((float4*)(out + (size_t)t*D_))[c] = o;
}

// ---------------- launch ----------------
extern "C" void kernel_launch(void* const* d_in, const int* in_sizes, int n_in,
                              void* d_out, int out_size)
{
    const float* x    = (const float*)d_in[0];
    const float* wq1  = (const float*)d_in[1];
    const float* bq1  = (const float*)d_in[2];
    const float* wq2  = (const float*)d_in[3];
    const float* bq2  = (const float*)d_in[4];
    const float* wk1  = (const float*)d_in[5];
    const float* bk1  = (const float*)d_in[6];
    const float* wk2  = (const float*)d_in[7];
    const float* bk2  = (const float*)d_in[8];
    const float* wv1  = (const float*)d_in[9];
    const float* bv1  = (const float*)d_in[10];
    const float* wv2  = (const float*)d_in[11];
    const float* bv2  = (const float*)d_in[12];
    const float* wo   = (const float*)d_in[13];
    const float* bo   = (const float*)d_in[14];
    const float* ln1g = (const float*)d_in[15];
    const float* ln1b = (const float*)d_in[16];
    const float* ln2g = (const float*)d_in[17];
    const float* ln2b = (const float*)d_in[18];
    const float* gw   = (const float*)d_in[19];
    const float* gb   = (const float*)d_in[20];
    const float* ew1  = (const float*)d_in[21];
    const float* eb1  = (const float*)d_in[22];
    const float* ew2  = (const float*)d_in[23];
    const float* eb2  = (const float*)d_in[24];
    const float* ew3  = (const float*)d_in[25];
    const float* eb3  = (const float*)d_in[26];
    float* out = (float*)d_out;

    dim3 gDD(TOK/BM, D_/BN);   // 64 x 16

    // x2 = LN1(x)
    ln_kernel<<<TOK, 256>>>(x, ln1g, ln1b);
    // q,k,v gated projections (phi on q,k)
    gated_proj_kernel<<<gDD, 256>>>(wq1, bq1, wq2, bq2, 0, 1);
    gated_proj_kernel<<<gDD, 256>>>(wk1, bk1, wk2, bk2, 1, 1);
    gated_proj_kernel<<<gDD, 256>>>(wv1, bv1, wv2, bv2, 2, 0);
    // linear attention
    kv_partial_kernel<<<dim3(32, 8), 256>>>();
    kv_reduce_kernel<<<(32*DK_*DK_ + 32*DK_ + 255)/256, 256>>>();
    attn_apply_kernel<<<dim3(32, S_/64), 256>>>();
    // out = attn@wo + bo + x
    out_proj_kernel<<<gDD, 256>>>(wo, bo, x, out);
    // x2 = LN2(out)
    ln_kernel<<<TOK, 256>>>(out, ln2g, ln2b);
    // MoE routing
    zero_cnt_kernel<<<1, 32>>>();
    routing_kernel<<<TOK/8, 256>>>(gw, gb);
    offsets_kernel<<<1, 1>>>();
    zero_xg_kernel<<<CAP_ROWS*D_/1024, 256>>>();
    place_gather_kernel<<<TOK*2, 256>>>();
    // expert GEMMs on gathered rows
    moe_h_kernel<<<dim3(CAP_ROWS/BM, F_/BN), 256>>>(ew1, eb1, ew3, eb3);
    moe_y_kernel<<<dim3(CAP_ROWS/BM, D_/BN), 256>>>(ew2, eb2);
    // scatter-combine into residual
    combine_kernel<<<TOK, 256>>>(out);
}

// round 4
// speedup vs baseline: 4.3430x; 4.3430x over previous
#include <cuda_runtime.h>
#include <cuda_fp16.h>
#include <math.h>
#include <stdint.h>

#define B_   2
#define S_   2048
#define D_   1024
#define H_   16
#define DK_  64
#define F_   4096
#define E_   8
#define TOK  (B_*S_)
#define CAP_ROWS (TOK*2 + E_*128)

#define KC   32               // k per chunk (halves)
#define SROW 40               // padded halves per smem row (80B)
#define TILE_HB (128*SROW*2)  // 10240 bytes per 128x32 tile
#define NTH  512

// ---------------- scratch ----------------
__device__ __align__(128) float  g_x2[TOK*D_];
__device__ __align__(128) __half g_x2h[TOK*D_];
__device__ __align__(128) float  g_q [TOK*D_];
__device__ __align__(128) float  g_k [TOK*D_];
__device__ __align__(128) float  g_v [TOK*D_];
__device__ __align__(128) __half g_ah[TOK*D_];
__device__ __align__(128) float  g_kvp[32*8*DK_*DK_];
__device__ __align__(128) float  g_kv [32*DK_*DK_];
__device__ __align__(128) float  g_ksp[32*8*DK_];
__device__ __align__(128) float  g_ks [32*DK_];
__device__ __align__(128) __half g_xgh[(size_t)CAP_ROWS*D_];
__device__ __align__(128) __half g_hh[(size_t)CAP_ROWS*F_];
__device__ __align__(128) float  g_y [(size_t)CAP_ROWS*D_];
__device__ __align__(128) __half g_wd[7*(size_t)D_*D_];     // q1,q2,k1,k2,v1,v2,o  as [N][K]
__device__ __align__(128) __half g_e1[8*(size_t)F_*D_];
__device__ __align__(128) __half g_e3[8*(size_t)F_*D_];
__device__ __align__(128) __half g_e2[8*(size_t)D_*F_];
__device__ int   g_cnt[E_];
__device__ int   g_off[E_+1];
__device__ int   g_cur[E_];
__device__ int   g_topi[TOK*2];
__device__ float g_topw[TOK*2];
__device__ int   g_row[TOK*2];

// ---------------- helpers ----------------
__device__ __forceinline__ uint32_t smem_u32(const void* p) {
    uint32_t a;
    asm("{ .reg .u64 t; cvta.to.shared.u64 t, %1; cvt.u32.u64 %0, t; }" : "=r"(a) : "l"(p));
    return a;
}
__device__ __forceinline__ float silu_gate(float a, float c) {
    return a / (1.f + expf(-a)) * c;
}
__device__ __forceinline__ float phi1(float x) { return x > 0.f ? x + 1.f : expf(x); }

__device__ __forceinline__ void cp16(uint32_t s, const void* g) {
    asm volatile("cp.async.cg.shared.global [%0], [%1], 16;" :: "r"(s), "l"(g) : "memory");
}

#define LDSM4(r, addr) \
    asm volatile("ldmatrix.sync.aligned.m8n8.x4.shared.b16 {%0,%1,%2,%3}, [%4];" \
        : "=r"((r)[0]), "=r"((r)[1]), "=r"((r)[2]), "=r"((r)[3]) : "r"(addr))
#define LDSM2(r, addr) \
    asm volatile("ldmatrix.sync.aligned.m8n8.x2.shared.b16 {%0,%1}, [%2];" \
        : "=r"((r)[0]), "=r"((r)[1]) : "r"(addr))
#define MMA_F16(c, a, b) \
    asm volatile("mma.sync.aligned.m16n8k16.row.col.f32.f16.f16.f32 " \
        "{%0,%1,%2,%3}, {%4,%5,%6,%7}, {%8,%9}, {%0,%1,%2,%3};" \
        : "+f"((c)[0]), "+f"((c)[1]), "+f"((c)[2]), "+f"((c)[3]) \
        : "r"((a)[0]), "r"((a)[1]), "r"((a)[2]), "r"((a)[3]), "r"((b)[0]), "r"((b)[1]))

// ---------------- mma.sync GEMM core ----------------
// Block tile 128x128 (x2 for DUAL), 512 threads, warp tile 32x32 per GEMM.
// A [M x K] row-major half; B [N x K] row-major half (i.e. W^T); C += A * B^T.
template<int DUAL>
__device__ __forceinline__ void ld_chunk(
    const __half* A, int lda, const __half* B0, const __half* B1, int ldb,
    int k0, uint32_t st, int tid)
{
    const int r = tid >> 2;
    const int c = (tid & 3) * 8;
    const uint32_t so = (uint32_t)(r * SROW + c) * 2;
    cp16(st + so, A + (size_t)r * lda + k0 + c);
    cp16(st + TILE_HB + so, B0 + (size_t)r * ldb + k0 + c);
    if (DUAL) cp16(st + 2 * TILE_HB + so, B1 + (size_t)r * ldb + k0 + c);
    asm volatile("cp.async.commit_group;" ::: "memory");
}

template<int DUAL>
__device__ __forceinline__ void compute_chunk(
    uint32_t st, float (&acc0)[2][4][4], float (&acc1)[2][4][4],
    int wm, int wn, int lane)
{
    const uint32_t aoff = (uint32_t)(((lane & 7) + ((lane >> 3) & 1) * 8) * SROW + (lane >> 4) * 8) * 2;
    const int lb = lane & 15;
    const uint32_t boff = (uint32_t)((lb & 7) * SROW + ((lb >> 3) & 1) * 8) * 2;
    #pragma unroll
    for (int ks = 0; ks < 2; ks++) {
        uint32_t a[2][4];
        #pragma unroll
        for (int mt = 0; mt < 2; mt++) {
            uint32_t addr = st + (uint32_t)((wm * 32 + mt * 16) * SROW + ks * 16) * 2 + aoff;
            LDSM4(a[mt], addr);
        }
        #pragma unroll
        for (int nt = 0; nt < 4; nt++) {
            uint32_t b[2];
            uint32_t addr = st + TILE_HB + (uint32_t)((wn * 32 + nt * 8) * SROW + ks * 16) * 2 + boff;
            LDSM2(b, addr);
            MMA_F16(acc0[0][nt], a[0], b);
            MMA_F16(acc0[1][nt], a[1], b);
        }
        if (DUAL) {
            #pragma unroll
            for (int nt = 0; nt < 4; nt++) {
                uint32_t b[2];
                uint32_t addr = st + 2 * TILE_HB + (uint32_t)((wn * 32 + nt * 8) * SROW + ks * 16) * 2 + boff;
                LDSM2(b, addr);
                MMA_F16(acc1[0][nt], a[0], b);
                MMA_F16(acc1[1][nt], a[1], b);
            }
        }
    }
}

template<int DUAL>
__device__ __forceinline__ void mma_mainloop(
    const __half* A, int lda, const __half* B0, const __half* B1, int ldb,
    int K, uint32_t sm, float (&acc0)[2][4][4], float (&acc1)[2][4][4])
{
    const int tid = threadIdx.x;
    const int lane = tid & 31, wid = tid >> 5;
    const int wm = wid & 3, wn = wid >> 2;
    const uint32_t STAGE = (DUAL ? 3 : 2) * TILE_HB;
    const int NC = K / KC;
    ld_chunk<DUAL>(A, lda, B0, B1, ldb, 0, sm, tid);
    for (int k = 0; k < NC; k++) {
        if (k + 1 < NC) {
            ld_chunk<DUAL>(A, lda, B0, B1, ldb, (k + 1) * KC, sm + (uint32_t)((k + 1) & 1) * STAGE, tid);
            asm volatile("cp.async.wait_group 1;" ::: "memory");
        } else {
            asm volatile("cp.async.wait_group 0;" ::: "memory");
        }
        __syncthreads();
        compute_chunk<DUAL>(sm + (uint32_t)(k & 1) * STAGE, acc0, acc1, wm, wn, lane);
        __syncthreads();
    }
}

// ---------------- GEMM kernels ----------------
#define SMEM_DUAL   (2*3*TILE_HB)   // 61440
#define SMEM_SINGLE (2*2*TILE_HB)   // 40960

// C = maybe_phi( silu(x2@W1+b1) * (x2@W2+b2) )
__global__ void __launch_bounds__(NTH, 1) mm_gated_kernel(
    const __half* __restrict__ w1t, const __half* __restrict__ w2t,
    const float* __restrict__ bias1, const float* __restrict__ bias2,
    float* __restrict__ C, int applyPhi)
{
    extern __shared__ __align__(128) char smem[];
    uint32_t sm = smem_u32(smem);
    const int bm0 = blockIdx.x * 128, bn0 = blockIdx.y * 128;
    float acc0[2][4][4] = {}, acc1[2][4][4] = {};
    mma_mainloop<1>(g_x2h + (size_t)bm0 * D_, D_,
                    w1t + (size_t)bn0 * D_, w2t + (size_t)bn0 * D_, D_,
                    D_, sm, acc0, acc1);
    const int lane = threadIdx.x & 31, wid = threadIdx.x >> 5;
    const int wm = wid & 3, wn = wid >> 2;
    const int quad = lane >> 2, tq = lane & 3;
    #pragma unroll
    for (int mt = 0; mt < 2; mt++) {
        #pragma unroll
        for (int nt = 0; nt < 4; nt++) {
            const int col = bn0 + wn * 32 + nt * 8 + tq * 2;
            const int r0 = bm0 + wm * 32 + mt * 16 + quad;
            float2 bb1 = *(const float2*)(bias1 + col);
            float2 bb2 = *(const float2*)(bias2 + col);
            float2 v;
            v.x = silu_gate(acc0[mt][nt][0] + bb1.x, acc1[mt][nt][0] + bb2.x);
            v.y = silu_gate(acc0[mt][nt][1] + bb1.y, acc1[mt][nt][1] + bb2.y);
            if (applyPhi) { v.x = phi1(v.x); v.y = phi1(v.y); }
            *(float2*)(C + (size_t)r0 * D_ + col) = v;
            v.x = silu_gate(acc0[mt][nt][2] + bb1.x, acc1[mt][nt][2] + bb2.x);
            v.y = silu_gate(acc0[mt][nt][3] + bb1.y, acc1[mt][nt][3] + bb2.y);
            if (applyPhi) { v.x = phi1(v.x); v.y = phi1(v.y); }
            *(float2*)(C + (size_t)(r0 + 8) * D_ + col) = v;
        }
    }
}

// out = attn @ wo + bo + residual
__global__ void __launch_bounds__(NTH, 1) mm_out_kernel(
    const __half* __restrict__ wt, const float* __restrict__ bias,
    const float* __restrict__ res, float* __restrict__ C)
{
    extern __shared__ __align__(128) char smem[];
    uint32_t sm = smem_u32(smem);
    const int bm0 = blockIdx.x * 128, bn0 = blockIdx.y * 128;
    float acc0[2][4][4] = {}, acc1[2][4][4];
    mma_mainloop<0>(g_ah + (size_t)bm0 * D_, D_,
                    wt + (size_t)bn0 * D_, (const __half*)0, D_,
                    D_, sm, acc0, acc1);
    const int lane = threadIdx.x & 31, wid = threadIdx.x >> 5;
    const int wm = wid & 3, wn = wid >> 2;
    const int quad = lane >> 2, tq = lane & 3;
    #pragma unroll
    for (int mt = 0; mt < 2; mt++) {
        #pragma unroll
        for (int nt = 0; nt < 4; nt++) {
            const int col = bn0 + wn * 32 + nt * 8 + tq * 2;
            const int r0 = bm0 + wm * 32 + mt * 16 + quad;
            float2 bb = *(const float2*)(bias + col);
            float2 rr0 = *(const float2*)(res + (size_t)r0 * D_ + col);
            float2 rr1 = *(const float2*)(res + (size_t)(r0 + 8) * D_ + col);
            float2 v;
            v.x = acc0[mt][nt][0] + bb.x + rr0.x;
            v.y = acc0[mt][nt][1] + bb.y + rr0.y;
            *(float2*)(C + (size_t)r0 * D_ + col) = v;
            v.x = acc0[mt][nt][2] + bb.x + rr1.x;
            v.y = acc0[mt][nt][3] + bb.y + rr1.y;
            *(float2*)(C + (size_t)(r0 + 8) * D_ + col) = v;
        }
    }
}

// h = silu(xg@w1[e]+b1[e]) * (xg@w3[e]+b3[e])  -> half
__global__ void __launch_bounds__(NTH, 1) mm_moeh_kernel(
    const float* __restrict__ eb1, const float* __restrict__ eb3)
{
    const int bm0 = blockIdx.x * 128;
    if (bm0 >= g_off[E_]) return;
    int e = 0;
    #pragma unroll
    for (int i = 0; i < E_; i++) if (bm0 >= g_off[i + 1]) e = i + 1;
    extern __shared__ __align__(128) char smem[];
    uint32_t sm = smem_u32(smem);
    const int bn0 = blockIdx.y * 128;
    const size_t wb = (size_t)e * F_ * D_ + (size_t)bn0 * D_;
    float acc0[2][4][4] = {}, acc1[2][4][4] = {};
    mma_mainloop<1>(g_xgh + (size_t)bm0 * D_, D_, g_e1 + wb, g_e3 + wb, D_,
                    D_, sm, acc0, acc1);
    const int lane = threadIdx.x & 31, wid = threadIdx.x >> 5;
    const int wm = wid & 3, wn = wid >> 2;
    const int quad = lane >> 2, tq = lane & 3;
    const float* b1 = eb1 + (size_t)e * F_;
    const float* b3 = eb3 + (size_t)e * F_;
    #pragma unroll
    for (int mt = 0; mt < 2; mt++) {
        #pragma unroll
        for (int nt = 0; nt < 4; nt++) {
            const int col = bn0 + wn * 32 + nt * 8 + tq * 2;
            const int r0 = bm0 + wm * 32 + mt * 16 + quad;
            float2 bb1 = *(const float2*)(b1 + col);
            float2 bb3 = *(const float2*)(b3 + col);
            float v0 = silu_gate(acc0[mt][nt][0] + bb1.x, acc1[mt][nt][0] + bb3.x);
            float v1 = silu_gate(acc0[mt][nt][1] + bb1.y, acc1[mt][nt][1] + bb3.y);
            *(__half2*)(g_hh + (size_t)r0 * F_ + col) = __floats2half2_rn(v0, v1);
            v0 = silu_gate(acc0[mt][nt][2] + bb1.x, acc1[mt][nt][2] + bb3.x);
            v1 = silu_gate(acc0[mt][nt][3] + bb1.y, acc1[mt][nt][3] + bb3.y);
            *(__half2*)(g_hh + (size_t)(r0 + 8) * F_ + col) = __floats2half2_rn(v0, v1);
        }
    }
}

// y = h @ w2[e] + b2[e]
__global__ void __launch_bounds__(NTH, 1) mm_moey_kernel(const float* __restrict__ eb2)
{
    const int bm0 = blockIdx.x * 128;
    if (bm0 >= g_off[E_]) return;
    int e = 0;
    #pragma unroll
    for (int i = 0; i < E_; i++) if (bm0 >= g_off[i + 1]) e = i + 1;
    extern __shared__ __align__(128) char smem[];
    uint32_t sm = smem_u32(smem);
    const int bn0 = blockIdx.y * 128;
    const size_t wb = (size_t)e * D_ * F_ + (size_t)bn0 * F_;
    float acc0[2][4][4] = {}, acc1[2][4][4];
    mma_mainloop<0>(g_hh + (size_t)bm0 * F_, F_, g_e2 + wb, (const __half*)0, F_,
                    F_, sm, acc0, acc1);
    const int lane = threadIdx.x & 31, wid = threadIdx.x >> 5;
    const int wm = wid & 3, wn = wid >> 2;
    const int quad = lane >> 2, tq = lane & 3;
    const float* b2 = eb2 + (size_t)e * D_;
    #pragma unroll
    for (int mt = 0; mt < 2; mt++) {
        #pragma unroll
        for (int nt = 0; nt < 4; nt++) {
            const int col = bn0 + wn * 32 + nt * 8 + tq * 2;
            const int r0 = bm0 + wm * 32 + mt * 16 + quad;
            float2 bb = *(const float2*)(b2 + col);
            float2 v;
            v.x = acc0[mt][nt][0] + bb.x;
            v.y = acc0[mt][nt][1] + bb.y;
            *(float2*)(g_y + (size_t)r0 * D_ + col) = v;
            v.x = acc0[mt][nt][2] + bb.x;
            v.y = acc0[mt][nt][3] + bb.y;
            *(float2*)(g_y + (size_t)(r0 + 8) * D_ + col) = v;
        }
    }
}

// ---------------- conversions ----------------
// transpose [K,N] fp32 -> [N,K] half ; batched via blockIdx.z
__global__ void __launch_bounds__(256) convT_kernel(
    const float* __restrict__ W, __half* __restrict__ T, int K, int N)
{
    __shared__ float t[32][33];
    const size_t zi = (size_t)blockIdx.z * K * N;
    const int k0 = blockIdx.y * 32, n0 = blockIdx.x * 32;
    const int r = threadIdx.x >> 3, c4 = (threadIdx.x & 7) * 4;
    float4 v = *(const float4*)(W + zi + (size_t)(k0 + r) * N + n0 + c4);
    t[r][c4 + 0] = v.x; t[r][c4 + 1] = v.y; t[r][c4 + 2] = v.z; t[r][c4 + 3] = v.w;
    __syncthreads();
    __half2 p0 = __floats2half2_rn(t[c4 + 0][r], t[c4 + 1][r]);
    __half2 p1 = __floats2half2_rn(t[c4 + 2][r], t[c4 + 3][r]);
    size_t ob = zi + (size_t)(n0 + r) * K + k0 + c4;
    ((__half2*)(T + ob))[0] = p0;
    ((__half2*)(T + ob))[1] = p1;
}

// ---------------- non-GEMM kernels ----------------
__global__ void __launch_bounds__(256) ln_kernel(
    const float* __restrict__ x, const float* __restrict__ g, const float* __restrict__ b)
{
    __shared__ float rs[256], rq[256];
    const int t = blockIdx.x, tid = threadIdx.x;
    float4 v = ((const float4*)(x + (size_t)t * D_))[tid];
    rs[tid] = v.x + v.y + v.z + v.w;
    rq[tid] = v.x * v.x + v.y * v.y + v.z * v.z + v.w * v.w;
    __syncthreads();
    for (int o = 128; o > 0; o >>= 1) {
        if (tid < o) { rs[tid] += rs[tid + o]; rq[tid] += rq[tid + o]; }
        __syncthreads();
    }
    float mean = rs[0] * (1.f / D_);
    float var  = rq[0] * (1.f / D_) - mean * mean;
    float inv  = rsqrtf(var + 1e-5f);
    float4 gg = ((const float4*)g)[tid];
    float4 bb = ((const float4*)b)[tid];
    float4 o4;
    o4.x = (v.x - mean) * inv * gg.x + bb.x;
    o4.y = (v.y - mean) * inv * gg.y + bb.y;
    o4.z = (v.z - mean) * inv * gg.z + bb.z;
    o4.w = (v.w - mean) * inv * gg.w + bb.w;
    ((float4*)(g_x2 + (size_t)t * D_))[tid] = o4;
    size_t ob = (size_t)t * D_ + tid * 4;
    ((__half2*)(g_x2h + ob))[0] = __floats2half2_rn(o4.x, o4.y);
    ((__half2*)(g_x2h + ob))[1] = __floats2half2_rn(o4.z, o4.w);
}

__global__ void __launch_bounds__(256) kv_partial_kernel()
{
    __shared__ float pk[DK_], pv[DK_];
    const int bh = blockIdx.x, c = blockIdx.y;
    const int b = bh >> 4, h = bh & 15;
    const int tid = threadIdx.x;
    const int d = tid >> 2, eg = tid & 3;
    float acc[16];
    #pragma unroll
    for (int j = 0; j < 16; j++) acc[j] = 0.f;
    float ks = 0.f;
    for (int s = c * 256; s < c * 256 + 256; s++) {
        size_t base = ((size_t)(b * S_ + s)) * D_ + h * DK_;
        if (tid < 64)       pk[tid]      = g_k[base + tid];
        else if (tid < 128) pv[tid - 64] = g_v[base + tid - 64];
        __syncthreads();
        float kd = pk[d];
        #pragma unroll
        for (int j = 0; j < 16; j++) acc[j] += kd * pv[eg + 4 * j];
        if (eg == 0) ks += kd;
        __syncthreads();
    }
    size_t ob = ((size_t)(bh * 8 + c)) * DK_ * DK_;
    #pragma unroll
    for (int j = 0; j < 16; j++) g_kvp[ob + d * DK_ + eg + 4 * j] = acc[j];
    if (eg == 0) g_ksp[(bh * 8 + c) * DK_ + d] = ks;
}

__global__ void kv_reduce_kernel()
{
    int i = blockIdx.x * 256 + threadIdx.x;
    if (i < 32 * DK_ * DK_) {
        int bh = i >> 12, r = i & 4095;
        float s = 0.f;
        #pragma unroll
        for (int c = 0; c < 8; c++) s += g_kvp[((size_t)(bh * 8 + c)) * 4096 + r];
        g_kv[i] = s;
    }
    int j = i - 32 * DK_ * DK_;
    if (j >= 0 && j < 32 * DK_) {
        int bh = j >> 6, d = j & 63;
        float s = 0.f;
        #pragma unroll
        for (int c = 0; c < 8; c++) s += g_ksp[(bh * 8 + c) * DK_ + d];
        g_ks[j] = s;
    }
}

__global__ void __launch_bounds__(256) attn_apply_kernel()
{
    __shared__ float kvs[DK_*DK_];
    __shared__ float kss[DK_];
    __shared__ float qs[4*DK_];
    const int bh = blockIdx.x;
    const int b = bh >> 4, h = bh & 15;
    const int tid = threadIdx.x;
    for (int i = tid; i < DK_ * DK_; i += 256) kvs[i] = g_kv[(size_t)bh * DK_ * DK_ + i];
    if (tid < DK_) kss[tid] = g_ks[bh * DK_ + tid];
    __syncthreads();
    const int sl = tid >> 6, e = tid & 63;
    const int sbase = blockIdx.y * 64;
    for (int pass = 0; pass < 16; pass++) {
        int s = sbase + pass * 4 + sl;
        qs[tid] = g_q[((size_t)(b * S_ + s)) * D_ + h * DK_ + e];
        __syncthreads();
        float acc = 0.f, qk = 0.f;
        #pragma unroll
        for (int d = 0; d < DK_; d++) {
            float qd = qs[sl * DK_ + d];
            acc += qd * kvs[d * DK_ + e];
            qk  += qd * kss[d];
        }
        g_ah[((size_t)(b * S_ + s)) * D_ + h * DK_ + e] = __float2half(acc / (qk + 1e-6f));
        __syncthreads();
    }
}

__global__ void zero_cnt_kernel() { if (threadIdx.x < E_) g_cnt[threadIdx.x] = 0; }

__global__ void zero_xg_kernel()
{
    size_t i = (size_t)blockIdx.x * 256 + threadIdx.x;
    ((uint4*)g_xgh)[i] = make_uint4(0u, 0u, 0u, 0u);
}

__global__ void __launch_bounds__(256) routing_kernel(
    const float* __restrict__ gw, const float* __restrict__ gb)
{
    const int lane = threadIdx.x & 31;
    const int warp = threadIdx.x >> 5;
    const int t = blockIdx.x * 8 + warp;
    const float* xr = g_x2 + (size_t)t * D_;
    float lg[8];
    #pragma unroll
    for (int e = 0; e < 8; e++) lg[e] = 0.f;
    for (int d = lane; d < D_; d += 32) {
        float xv = xr[d];
        const float4* wr = (const float4*)(gw + (size_t)d * 8);
        float4 w0 = wr[0], w1 = wr[1];
        lg[0] += xv * w0.x; lg[1] += xv * w0.y; lg[2] += xv * w0.z; lg[3] += xv * w0.w;
        lg[4] += xv * w1.x; lg[5] += xv * w1.y; lg[6] += xv * w1.z; lg[7] += xv * w1.w;
    }
    #pragma unroll
    for (int o = 16; o > 0; o >>= 1) {
        #pragma unroll
        for (int e = 0; e < 8; e++) lg[e] += __shfl_xor_sync(0xffffffffu, lg[e], o);
    }
    if (lane == 0) {
        float p[8], mx = -1e30f;
        #pragma unroll
        for (int e = 0; e < 8; e++) { lg[e] += gb[e]; mx = fmaxf(mx, lg[e]); }
        float se = 0.f;
        #pragma unroll
        for (int e = 0; e < 8; e++) { p[e] = expf(lg[e] - mx); se += p[e]; }
        int i0 = 0;
        #pragma unroll
        for (int e = 1; e < 8; e++) if (p[e] > p[i0]) i0 = e;
        int i1 = (i0 == 0) ? 1 : 0;
        #pragma unroll
        for (int e = 0; e < 8; e++) if (e != i0 && p[e] > p[i1]) i1 = e;
        float v0 = p[i0] / se, v1 = p[i1] / se;
        float inv = 1.f / (v0 + v1 + 1e-6f);
        g_topi[t*2]   = i0; g_topi[t*2+1] = i1;
        g_topw[t*2]   = v0 * inv; g_topw[t*2+1] = v1 * inv;
        atomicAdd(&g_cnt[i0], 1);
        atomicAdd(&g_cnt[i1], 1);
    }
}

__global__ void offsets_kernel()
{
    if (threadIdx.x == 0) {
        int o = 0;
        for (int e = 0; e < E_; e++) {
            g_off[e] = o;
            o += (g_cnt[e] + 127) & ~127;
            g_cur[e] = 0;
        }
        g_off[E_] = o;
    }
}

__global__ void __launch_bounds__(256) place_gather_kernel()
{
    const int slot = blockIdx.x;
    const int t = slot >> 1;
    __shared__ int row_s;
    if (threadIdx.x == 0) {
        int e = g_topi[slot];
        int pos = atomicAdd(&g_cur[e], 1);
        int row = g_off[e] + pos;
        g_row[slot] = row;
        row_s = row;
    }
    __syncthreads();
    int row = row_s;
    ((uint2*)(g_xgh + (size_t)row * D_))[threadIdx.x] =
        ((const uint2*)(g_x2h + (size_t)t * D_))[threadIdx.x];
}

__global__ void __launch_bounds__(256) combine_kernel(float* __restrict__ out)
{
    const int t = blockIdx.x;
    const int r0 = g_row[2*t], r1 = g_row[2*t+1];
    const float w0 = g_topw[2*t], w1 = g_topw[2*t+1];
    const int c = threadIdx.x;
    float4 o  = ((float4*)(out + (size_t)t * D_))[c];
    float4 y0 = ((const float4*)(g_y + (size_t)r0 * D_))[c];
    float4 y1 = ((const float4*)(g_y + (size_t)r1 * D_))[c];
    o.x += w0 * y0.x + w1 * y1.x;
    o.y += w0 * y0.y + w1 * y1.y;
    o.z += w0 * y0.z + w1 * y1.z;
    o.w += w0 * y0.w + w1 * y1.w;
    ((float4*)(out + (size_t)t * D_))[c] = o;
}

// ---------------- launch ----------------
extern "C" void kernel_launch(void* const* d_in, const int* in_sizes, int n_in,
                              void* d_out, int out_size)
{
    const float* x    = (const float*)d_in[0];
    const float* wq1  = (const float*)d_in[1];
    const float* bq1  = (const float*)d_in[2];
    const float* wq2  = (const float*)d_in[3];
    const float* bq2  = (const float*)d_in[4];
    const float* wk1  = (const float*)d_in[5];
    const float* bk1  = (const float*)d_in[6];
    const float* wk2  = (const float*)d_in[7];
    const float* bk2  = (const float*)d_in[8];
    const float* wv1  = (const float*)d_in[9];
    const float* bv1  = (const float*)d_in[10];
    const float* wv2  = (const float*)d_in[11];
    const float* bv2  = (const float*)d_in[12];
    const float* wo   = (const float*)d_in[13];
    const float* bo   = (const float*)d_in[14];
    const float* ln1g = (const float*)d_in[15];
    const float* ln1b = (const float*)d_in[16];
    const float* ln2g = (const float*)d_in[17];
    const float* ln2b = (const float*)d_in[18];
    const float* gw   = (const float*)d_in[19];
    const float* gb   = (const float*)d_in[20];
    const float* ew1  = (const float*)d_in[21];
    const float* eb1  = (const float*)d_in[22];
    const float* ew2  = (const float*)d_in[23];
    const float* eb2  = (const float*)d_in[24];
    const float* ew3  = (const float*)d_in[25];
    const float* eb3  = (const float*)d_in[26];
    float* out = (float*)d_out;

    cudaFuncSetAttribute(mm_gated_kernel, cudaFuncAttributeMaxDynamicSharedMemorySize, SMEM_DUAL);
    cudaFuncSetAttribute(mm_moeh_kernel,  cudaFuncAttributeMaxDynamicSharedMemorySize, SMEM_DUAL);
    cudaFuncSetAttribute(mm_out_kernel,   cudaFuncAttributeMaxDynamicSharedMemorySize, SMEM_SINGLE);
    cudaFuncSetAttribute(mm_moey_kernel,  cudaFuncAttributeMaxDynamicSharedMemorySize, SMEM_SINGLE);

    __half *wd, *e1, *e3, *e2;
    float *qp, *kp, *vp;
    cudaGetSymbolAddress((void**)&wd, g_wd);
    cudaGetSymbolAddress((void**)&e1, g_e1);
    cudaGetSymbolAddress((void**)&e3, g_e3);
    cudaGetSymbolAddress((void**)&e2, g_e2);
    cudaGetSymbolAddress((void**)&qp, g_q);
    cudaGetSymbolAddress((void**)&kp, g_k);
    cudaGetSymbolAddress((void**)&vp, g_v);

    const size_t DD = (size_t)D_ * D_;
    dim3 gT(D_ / 32, D_ / 32);
    convT_kernel<<<gT, 256>>>(wq1, wd + 0 * DD, D_, D_);
    convT_kernel<<<gT, 256>>>(wq2, wd + 1 * DD, D_, D_);
    convT_kernel<<<gT, 256>>>(wk1, wd + 2 * DD, D_, D_);
    convT_kernel<<<gT, 256>>>(wk2, wd + 3 * DD, D_, D_);
    convT_kernel<<<gT, 256>>>(wv1, wd + 4 * DD, D_, D_);
    convT_kernel<<<gT, 256>>>(wv2, wd + 5 * DD, D_, D_);
    convT_kernel<<<gT, 256>>>(wo,  wd + 6 * DD, D_, D_);
    convT_kernel<<<dim3(F_ / 32, D_ / 32, 8), 256>>>(ew1, e1, D_, F_);
    convT_kernel<<<dim3(F_ / 32, D_ / 32, 8), 256>>>(ew3, e3, D_, F_);
    convT_kernel<<<dim3(D_ / 32, F_ / 32, 8), 256>>>(ew2, e2, F_, D_);

    dim3 gDD(TOK / 128, D_ / 128);   // 32 x 8

    ln_kernel<<<TOK, 256>>>(x, ln1g, ln1b);
    mm_gated_kernel<<<gDD, NTH, SMEM_DUAL>>>(wd + 0 * DD, wd + 1 * DD, bq1, bq2, qp, 1);
    mm_gated_kernel<<<gDD, NTH, SMEM_DUAL>>>(wd + 2 * DD, wd + 3 * DD, bk1, bk2, kp, 1);
    mm_gated_kernel<<<gDD, NTH, SMEM_DUAL>>>(wd + 4 * DD, wd + 5 * DD, bv1, bv2, vp, 0);
    kv_partial_kernel<<<dim3(32, 8), 256>>>();
    kv_reduce_kernel<<<(32 * DK_ * DK_ + 32 * DK_ + 255) / 256, 256>>>();
    attn_apply_kernel<<<dim3(32, S_ / 64), 256>>>();
    mm_out_kernel<<<gDD, NTH, SMEM_SINGLE>>>(wd + 6 * DD, bo, x, out);
    ln_kernel<<<TOK, 256>>>(out, ln2g, ln2b);
    zero_cnt_kernel<<<1, 32>>>();
    routing_kernel<<<TOK / 8, 256>>>(gw, gb);
    offsets_kernel<<<1, 1>>>();
    zero_xg_kernel<<<(int)(((size_t)CAP_ROWS * D_) / 2048), 256>>>();
    place_gather_kernel<<<TOK * 2, 256>>>();
    mm_moeh_kernel<<<dim3(CAP_ROWS / 128, F_ / 128), NTH, SMEM_DUAL>>>(eb1, eb3);
    mm_moey_kernel<<<dim3(CAP_ROWS / 128, D_ / 128), NTH, SMEM_SINGLE>>>(eb2);
    combine_kernel<<<TOK, 256>>>(out);
}

// round 5
// speedup vs baseline: 4.9388x; 1.1372x over previous
#include <cuda_runtime.h>
#include <cuda_fp16.h>
#include <math.h>
#include <stdint.h>

#define B_   2
#define S_   2048
#define D_   1024
#define H_   16
#define DK_  64
#define F_   4096
#define E_   8
#define TOK  (B_*S_)
#define CAP_ROWS (TOK*2 + E_*128)

#define KC   32               // k per chunk (halves)
#define SROW 40               // padded halves per A smem row (80B)
#define TILE_AB (128*SROW*2)  // 10240 bytes: A tile 128x32
#define TILE_BB (32*256)      // 8192 bytes: B tile 32(k) x 128(n), swizzled
#define STG_D  (TILE_AB + 2*TILE_BB)  // 26624
#define STG_S  (TILE_AB + 1*TILE_BB)  // 18432
#define NTH  512

// ---------------- scratch ----------------
__device__ __align__(128) float  g_x2[TOK*D_];
__device__ __align__(128) __half g_x2h[TOK*D_];
__device__ __align__(128) float  g_q [TOK*D_];
__device__ __align__(128) float  g_k [TOK*D_];
__device__ __align__(128) float  g_v [TOK*D_];
__device__ __align__(128) __half g_ah[TOK*D_];
__device__ __align__(128) float  g_kvp[32*8*DK_*DK_];
__device__ __align__(128) float  g_kv [32*DK_*DK_];
__device__ __align__(128) float  g_ksp[32*8*DK_];
__device__ __align__(128) float  g_ks [32*DK_];
__device__ __align__(128) __half g_xgh[(size_t)CAP_ROWS*D_];
__device__ __align__(128) __half g_hh[(size_t)CAP_ROWS*F_];
__device__ __align__(128) float  g_y [(size_t)CAP_ROWS*D_];
__device__ __align__(128) __half g_wd[7*(size_t)D_*D_];     // fp16 copies, [K,N] layout
__device__ __align__(128) __half g_e1[8*(size_t)D_*F_];
__device__ __align__(128) __half g_e3[8*(size_t)D_*F_];
__device__ __align__(128) __half g_e2[8*(size_t)F_*D_];
__device__ int   g_cnt[E_];
__device__ int   g_off[E_+1];
__device__ int   g_cur[E_];
__device__ int   g_topi[TOK*2];
__device__ float g_topw[TOK*2];
__device__ int   g_row[TOK*2];

// ---------------- helpers ----------------
__device__ __forceinline__ uint32_t smem_u32(const void* p) {
    uint32_t a;
    asm("{ .reg .u64 t; cvta.to.shared.u64 t, %1; cvt.u32.u64 %0, t; }" : "=r"(a) : "l"(p));
    return a;
}
__device__ __forceinline__ float silu_gate(float a, float c) {
    return a / (1.f + expf(-a)) * c;
}
__device__ __forceinline__ float phi1(float x) { return x > 0.f ? x + 1.f : expf(x); }

__device__ __forceinline__ void cp16(uint32_t s, const void* g) {
    asm volatile("cp.async.cg.shared.global [%0], [%1], 16;" :: "r"(s), "l"(g) : "memory");
}

#define LDSM4(r, addr) \
    asm volatile("ldmatrix.sync.aligned.m8n8.x4.shared.b16 {%0,%1,%2,%3}, [%4];" \
        : "=r"((r)[0]), "=r"((r)[1]), "=r"((r)[2]), "=r"((r)[3]) : "r"(addr))
#define LDSM2T(r, addr) \
    asm volatile("ldmatrix.sync.aligned.m8n8.x2.trans.shared.b16 {%0,%1}, [%2];" \
        : "=r"((r)[0]), "=r"((r)[1]) : "r"(addr))
#define MMA_F16(c, a, b) \
    asm volatile("mma.sync.aligned.m16n8k16.row.col.f32.f16.f16.f32 " \
        "{%0,%1,%2,%3}, {%4,%5,%6,%7}, {%8,%9}, {%0,%1,%2,%3};" \
        : "+f"((c)[0]), "+f"((c)[1]), "+f"((c)[2]), "+f"((c)[3]) \
        : "r"((a)[0]), "r"((a)[1]), "r"((a)[2]), "r"((a)[3]), "r"((b)[0]), "r"((b)[1]))

// ---------------- mma.sync GEMM core ----------------
// A [M x K] row-major half (padded smem rows, regular ldmatrix).
// B [K x N] row-major half (weight natural layout), K-major swizzled smem
// tile + ldmatrix.x2.trans. C = A @ B.
template<int DUAL>
__device__ __forceinline__ void ld_chunk(
    const __half* A, int lda, const __half* B0, const __half* B1, int ldb,
    int k0, uint32_t st, int tid)
{
    // A: 128 rows x 32 halves
    const int r = tid >> 2;
    const int c = (tid & 3) * 8;
    cp16(st + (uint32_t)(r * SROW + c) * 2, A + (size_t)r * lda + k0 + c);
    // B: 32 k-rows x 128 n-cols (16B granules, XOR-swizzled by k)
    const int bk = tid >> 4;
    const int bg = tid & 15;
    const uint32_t bso = (uint32_t)bk * 256 + (uint32_t)((bg ^ (bk & 7)) << 4);
    const size_t go = (size_t)(k0 + bk) * ldb + bg * 8;
    cp16(st + TILE_AB + bso, B0 + go);
    if (DUAL) cp16(st + TILE_AB + TILE_BB + bso, B1 + go);
    asm volatile("cp.async.commit_group;" ::: "memory");
}

template<int DUAL>
__device__ __forceinline__ void compute_chunk(
    uint32_t st, float (&acc0)[2][4][4], float (&acc1)[2][4][4],
    int wm, int wn, int lane)
{
    const uint32_t aoff = (uint32_t)(((lane & 7) + ((lane >> 3) & 1) * 8) * SROW + (lane >> 4) * 8) * 2;
    const uint32_t stB0 = st + TILE_AB;
    const uint32_t stB1 = st + TILE_AB + TILE_BB;
    #pragma unroll
    for (int ks = 0; ks < 2; ks++) {
        uint32_t a[2][4];
        #pragma unroll
        for (int mt = 0; mt < 2; mt++) {
            uint32_t addr = st + (uint32_t)((wm * 32 + mt * 16) * SROW + ks * 16) * 2 + aoff;
            LDSM4(a[mt], addr);
        }
        const int kk = ks * 16 + (lane & 15);
        const uint32_t brow = (uint32_t)kk * 256;
        const uint32_t kx = (uint32_t)(kk & 7) << 4;
        #pragma unroll
        for (int nt = 0; nt < 4; nt++) {
            const uint32_t gy = ((uint32_t)(wn * 4 + nt) << 4) ^ kx;
            uint32_t b[2];
            LDSM2T(b, stB0 + brow + gy);
            MMA_F16(acc0[0][nt], a[0], b);
            MMA_F16(acc0[1][nt], a[1], b);
        }
        if (DUAL) {
            #pragma unroll
            for (int nt = 0; nt < 4; nt++) {
                const uint32_t gy = ((uint32_t)(wn * 4 + nt) << 4) ^ kx;
                uint32_t b[2];
                LDSM2T(b, stB1 + brow + gy);
                MMA_F16(acc1[0][nt], a[0], b);
                MMA_F16(acc1[1][nt], a[1], b);
            }
        }
    }
}

template<int DUAL>
__device__ __forceinline__ void mma_mainloop(
    const __half* A, int lda, const __half* B0, const __half* B1, int ldb,
    int K, uint32_t sm, float (&acc0)[2][4][4], float (&acc1)[2][4][4])
{
    const int tid = threadIdx.x;
    const int lane = tid & 31, wid = tid >> 5;
    const int wm = wid & 3, wn = wid >> 2;
    const uint32_t STAGE = DUAL ? STG_D : STG_S;
    const int NC = K / KC;
    ld_chunk<DUAL>(A, lda, B0, B1, ldb, 0, sm, tid);
    for (int k = 0; k < NC; k++) {
        if (k + 1 < NC) {
            ld_chunk<DUAL>(A, lda, B0, B1, ldb, (k + 1) * KC, sm + (uint32_t)((k + 1) & 1) * STAGE, tid);
            asm volatile("cp.async.wait_group 1;" ::: "memory");
        } else {
            asm volatile("cp.async.wait_group 0;" ::: "memory");
        }
        __syncthreads();
        compute_chunk<DUAL>(sm + (uint32_t)(k & 1) * STAGE, acc0, acc1, wm, wn, lane);
        __syncthreads();
    }
}

// ---------------- GEMM kernels ----------------
#define SMEM_DUAL   (2*STG_D)   // 53248
#define SMEM_SINGLE (2*STG_S)   // 36864

// C = maybe_phi( silu(x2@W1+b1) * (x2@W2+b2) )
__global__ void __launch_bounds__(NTH, 1) mm_gated_kernel(
    const __half* __restrict__ w1, const __half* __restrict__ w2,
    const float* __restrict__ bias1, const float* __restrict__ bias2,
    float* __restrict__ C, int applyPhi)
{
    extern __shared__ __align__(128) char smem[];
    uint32_t sm = smem_u32(smem);
    const int bm0 = blockIdx.x * 128, bn0 = blockIdx.y * 128;
    float acc0[2][4][4] = {}, acc1[2][4][4] = {};
    mma_mainloop<1>(g_x2h + (size_t)bm0 * D_, D_, w1 + bn0, w2 + bn0, D_,
                    D_, sm, acc0, acc1);
    const int lane = threadIdx.x & 31, wid = threadIdx.x >> 5;
    const int wm = wid & 3, wn = wid >> 2;
    const int quad = lane >> 2, tq = lane & 3;
    #pragma unroll
    for (int mt = 0; mt < 2; mt++) {
        #pragma unroll
        for (int nt = 0; nt < 4; nt++) {
            const int col = bn0 + wn * 32 + nt * 8 + tq * 2;
            const int r0 = bm0 + wm * 32 + mt * 16 + quad;
            float2 bb1 = *(const float2*)(bias1 + col);
            float2 bb2 = *(const float2*)(bias2 + col);
            float2 v;
            v.x = silu_gate(acc0[mt][nt][0] + bb1.x, acc1[mt][nt][0] + bb2.x);
            v.y = silu_gate(acc0[mt][nt][1] + bb1.y, acc1[mt][nt][1] + bb2.y);
            if (applyPhi) { v.x = phi1(v.x); v.y = phi1(v.y); }
            *(float2*)(C + (size_t)r0 * D_ + col) = v;
            v.x = silu_gate(acc0[mt][nt][2] + bb1.x, acc1[mt][nt][2] + bb2.x);
            v.y = silu_gate(acc0[mt][nt][3] + bb1.y, acc1[mt][nt][3] + bb2.y);
            if (applyPhi) { v.x = phi1(v.x); v.y = phi1(v.y); }
            *(float2*)(C + (size_t)(r0 + 8) * D_ + col) = v;
        }
    }
}

// out = attn @ wo + bo + residual
__global__ void __launch_bounds__(NTH, 1) mm_out_kernel(
    const __half* __restrict__ w, const float* __restrict__ bias,
    const float* __restrict__ res, float* __restrict__ C)
{
    extern __shared__ __align__(128) char smem[];
    uint32_t sm = smem_u32(smem);
    const int bm0 = blockIdx.x * 128, bn0 = blockIdx.y * 128;
    float acc0[2][4][4] = {}, acc1[2][4][4];
    mma_mainloop<0>(g_ah + (size_t)bm0 * D_, D_, w + bn0, (const __half*)0, D_,
                    D_, sm, acc0, acc1);
    const int lane = threadIdx.x & 31, wid = threadIdx.x >> 5;
    const int wm = wid & 3, wn = wid >> 2;
    const int quad = lane >> 2, tq = lane & 3;
    #pragma unroll
    for (int mt = 0; mt < 2; mt++) {
        #pragma unroll
        for (int nt = 0; nt < 4; nt++) {
            const int col = bn0 + wn * 32 + nt * 8 + tq * 2;
            const int r0 = bm0 + wm * 32 + mt * 16 + quad;
            float2 bb = *(const float2*)(bias + col);
            float2 rr0 = *(const float2*)(res + (size_t)r0 * D_ + col);
            float2 rr1 = *(const float2*)(res + (size_t)(r0 + 8) * D_ + col);
            float2 v;
            v.x = acc0[mt][nt][0] + bb.x + rr0.x;
            v.y = acc0[mt][nt][1] + bb.y + rr0.y;
            *(float2*)(C + (size_t)r0 * D_ + col) = v;
            v.x = acc0[mt][nt][2] + bb.x + rr1.x;
            v.y = acc0[mt][nt][3] + bb.y + rr1.y;
            *(float2*)(C + (size_t)(r0 + 8) * D_ + col) = v;
        }
    }
}

// h = silu(xg@w1[e]+b1[e]) * (xg@w3[e]+b3[e])  -> half
__global__ void __launch_bounds__(NTH, 1) mm_moeh_kernel(
    const float* __restrict__ eb1, const float* __restrict__ eb3)
{
    const int bm0 = blockIdx.x * 128;
    if (bm0 >= g_off[E_]) return;
    int e = 0;
    #pragma unroll
    for (int i = 0; i < E_; i++) if (bm0 >= g_off[i + 1]) e = i + 1;
    extern __shared__ __align__(128) char smem[];
    uint32_t sm = smem_u32(smem);
    const int bn0 = blockIdx.y * 128;
    const size_t wb = (size_t)e * D_ * F_ + bn0;
    float acc0[2][4][4] = {}, acc1[2][4][4] = {};
    mma_mainloop<1>(g_xgh + (size_t)bm0 * D_, D_, g_e1 + wb, g_e3 + wb, F_,
                    D_, sm, acc0, acc1);
    const int lane = threadIdx.x & 31, wid = threadIdx.x >> 5;
    const int wm = wid & 3, wn = wid >> 2;
    const int quad = lane >> 2, tq = lane & 3;
    const float* b1 = eb1 + (size_t)e * F_;
    const float* b3 = eb3 + (size_t)e * F_;
    #pragma unroll
    for (int mt = 0; mt < 2; mt++) {
        #pragma unroll
        for (int nt = 0; nt < 4; nt++) {
            const int col = bn0 + wn * 32 + nt * 8 + tq * 2;
            const int r0 = bm0 + wm * 32 + mt * 16 + quad;
            float2 bb1 = *(const float2*)(b1 + col);
            float2 bb3 = *(const float2*)(b3 + col);
            float v0 = silu_gate(acc0[mt][nt][0] + bb1.x, acc1[mt][nt][0] + bb3.x);
            float v1 = silu_gate(acc0[mt][nt][1] + bb1.y, acc1[mt][nt][1] + bb3.y);
            *(__half2*)(g_hh + (size_t)r0 * F_ + col) = __floats2half2_rn(v0, v1);
            v0 = silu_gate(acc0[mt][nt][2] + bb1.x, acc1[mt][nt][2] + bb3.x);
            v1 = silu_gate(acc0[mt][nt][3] + bb1.y, acc1[mt][nt][3] + bb3.y);
            *(__half2*)(g_hh + (size_t)(r0 + 8) * F_ + col) = __floats2half2_rn(v0, v1);
        }
    }
}

// y = h @ w2[e] + b2[e]
__global__ void __launch_bounds__(NTH, 1) mm_moey_kernel(const float* __restrict__ eb2)
{
    const int bm0 = blockIdx.x * 128;
    if (bm0 >= g_off[E_]) return;
    int e = 0;
    #pragma unroll
    for (int i = 0; i < E_; i++) if (bm0 >= g_off[i + 1]) e = i + 1;
    extern __shared__ __align__(128) char smem[];
    uint32_t sm = smem_u32(smem);
    const int bn0 = blockIdx.y * 128;
    const size_t wb = (size_t)e * F_ * D_ + bn0;
    float acc0[2][4][4] = {}, acc1[2][4][4];
    mma_mainloop<0>(g_hh + (size_t)bm0 * F_, F_, g_e2 + wb, (const __half*)0, D_,
                    F_, sm, acc0, acc1);
    const int lane = threadIdx.x & 31, wid = threadIdx.x >> 5;
    const int wm = wid & 3, wn = wid >> 2;
    const int quad = lane >> 2, tq = lane & 3;
    const float* b2 = eb2 + (size_t)e * D_;
    #pragma unroll
    for (int mt = 0; mt < 2; mt++) {
        #pragma unroll
        for (int nt = 0; nt < 4; nt++) {
            const int col = bn0 + wn * 32 + nt * 8 + tq * 2;
            const int r0 = bm0 + wm * 32 + mt * 16 + quad;
            float2 bb = *(const float2*)(b2 + col);
            float2 v;
            v.x = acc0[mt][nt][0] + bb.x;
            v.y = acc0[mt][nt][1] + bb.y;
            *(float2*)(g_y + (size_t)r0 * D_ + col) = v;
            v.x = acc0[mt][nt][2] + bb.x;
            v.y = acc0[mt][nt][3] + bb.y;
            *(float2*)(g_y + (size_t)(r0 + 8) * D_ + col) = v;
        }
    }
}

// ---------------- conversion: streaming fp32 -> fp16 ----------------
__global__ void __launch_bounds__(256) conv_kernel(
    const float* __restrict__ S, __half* __restrict__ Dst, int n8)
{
    int i = blockIdx.x * 256 + threadIdx.x;
    if (i >= n8) return;
    float4 a = ((const float4*)S)[2 * i];
    float4 b = ((const float4*)S)[2 * i + 1];
    __half2 h0 = __floats2half2_rn(a.x, a.y);
    __half2 h1 = __floats2half2_rn(a.z, a.w);
    __half2 h2 = __floats2half2_rn(b.x, b.y);
    __half2 h3 = __floats2half2_rn(b.z, b.w);
    uint4 o;
    o.x = *(uint32_t*)&h0; o.y = *(uint32_t*)&h1;
    o.z = *(uint32_t*)&h2; o.w = *(uint32_t*)&h3;
    ((uint4*)Dst)[i] = o;
}

// ---------------- non-GEMM kernels ----------------
__global__ void __launch_bounds__(256) ln_kernel(
    const float* __restrict__ x, const float* __restrict__ g, const float* __restrict__ b)
{
    __shared__ float rs[256], rq[256];
    const int t = blockIdx.x, tid = threadIdx.x;
    float4 v = ((const float4*)(x + (size_t)t * D_))[tid];
    rs[tid] = v.x + v.y + v.z + v.w;
    rq[tid] = v.x * v.x + v.y * v.y + v.z * v.z + v.w * v.w;
    __syncthreads();
    for (int o = 128; o > 0; o >>= 1) {
        if (tid < o) { rs[tid] += rs[tid + o]; rq[tid] += rq[tid + o]; }
        __syncthreads();
    }
    float mean = rs[0] * (1.f / D_);
    float var  = rq[0] * (1.f / D_) - mean * mean;
    float inv  = rsqrtf(var + 1e-5f);
    float4 gg = ((const float4*)g)[tid];
    float4 bb = ((const float4*)b)[tid];
    float4 o4;
    o4.x = (v.x - mean) * inv * gg.x + bb.x;
    o4.y = (v.y - mean) * inv * gg.y + bb.y;
    o4.z = (v.z - mean) * inv * gg.z + bb.z;
    o4.w = (v.w - mean) * inv * gg.w + bb.w;
    ((float4*)(g_x2 + (size_t)t * D_))[tid] = o4;
    size_t ob = (size_t)t * D_ + tid * 4;
    ((__half2*)(g_x2h + ob))[0] = __floats2half2_rn(o4.x, o4.y);
    ((__half2*)(g_x2h + ob))[1] = __floats2half2_rn(o4.z, o4.w);
}

__global__ void __launch_bounds__(256) kv_partial_kernel()
{
    __shared__ float pk[DK_], pv[DK_];
    const int bh = blockIdx.x, c = blockIdx.y;
    const int b = bh >> 4, h = bh & 15;
    const int tid = threadIdx.x;
    const int d = tid >> 2, eg = tid & 3;
    float acc[16];
    #pragma unroll
    for (int j = 0; j < 16; j++) acc[j] = 0.f;
    float ks = 0.f;
    for (int s = c * 256; s < c * 256 + 256; s++) {
        size_t base = ((size_t)(b * S_ + s)) * D_ + h * DK_;
        if (tid < 64)       pk[tid]      = g_k[base + tid];
        else if (tid < 128) pv[tid - 64] = g_v[base + tid - 64];
        __syncthreads();
        float kd = pk[d];
        #pragma unroll
        for (int j = 0; j < 16; j++) acc[j] += kd * pv[eg + 4 * j];
        if (eg == 0) ks += kd;
        __syncthreads();
    }
    size_t ob = ((size_t)(bh * 8 + c)) * DK_ * DK_;
    #pragma unroll
    for (int j = 0; j < 16; j++) g_kvp[ob + d * DK_ + eg + 4 * j] = acc[j];
    if (eg == 0) g_ksp[(bh * 8 + c) * DK_ + d] = ks;
}

__global__ void kv_reduce_kernel()
{
    int i = blockIdx.x * 256 + threadIdx.x;
    if (i < 32 * DK_ * DK_) {
        int bh = i >> 12, r = i & 4095;
        float s = 0.f;
        #pragma unroll
        for (int c = 0; c < 8; c++) s += g_kvp[((size_t)(bh * 8 + c)) * 4096 + r];
        g_kv[i] = s;
    }
    int j = i - 32 * DK_ * DK_;
    if (j >= 0 && j < 32 * DK_) {
        int bh = j >> 6, d = j & 63;
        float s = 0.f;
        #pragma unroll
        for (int c = 0; c < 8; c++) s += g_ksp[(bh * 8 + c) * DK_ + d];
        g_ks[j] = s;
    }
}

__global__ void __launch_bounds__(256) attn_apply_kernel()
{
    __shared__ float kvs[DK_*DK_];
    __shared__ float kss[DK_];
    __shared__ float qs[4*DK_];
    const int bh = blockIdx.x;
    const int b = bh >> 4, h = bh & 15;
    const int tid = threadIdx.x;
    for (int i = tid; i < DK_ * DK_; i += 256) kvs[i] = g_kv[(size_t)bh * DK_ * DK_ + i];
    if (tid < DK_) kss[tid] = g_ks[bh * DK_ + tid];
    __syncthreads();
    const int sl = tid >> 6, e = tid & 63;
    const int sbase = blockIdx.y * 64;
    for (int pass = 0; pass < 16; pass++) {
        int s = sbase + pass * 4 + sl;
        qs[tid] = g_q[((size_t)(b * S_ + s)) * D_ + h * DK_ + e];
        __syncthreads();
        float acc = 0.f, qk = 0.f;
        #pragma unroll
        for (int d = 0; d < DK_; d++) {
            float qd = qs[sl * DK_ + d];
            acc += qd * kvs[d * DK_ + e];
            qk  += qd * kss[d];
        }
        g_ah[((size_t)(b * S_ + s)) * D_ + h * DK_ + e] = __float2half(acc / (qk + 1e-6f));
        __syncthreads();
    }
}

__global__ void zero_cnt_kernel() { if (threadIdx.x < E_) g_cnt[threadIdx.x] = 0; }

__global__ void zero_xg_kernel()
{
    size_t i = (size_t)blockIdx.x * 256 + threadIdx.x;
    ((uint4*)g_xgh)[i] = make_uint4(0u, 0u, 0u, 0u);
}

__global__ void __launch_bounds__(256) routing_kernel(
    const float* __restrict__ gw, const float* __restrict__ gb)
{
    const int lane = threadIdx.x & 31;
    const int warp = threadIdx.x >> 5;
    const int t = blockIdx.x * 8 + warp;
    const float* xr = g_x2 + (size_t)t * D_;
    float lg[8];
    #pragma unroll
    for (int e = 0; e < 8; e++) lg[e] = 0.f;
    for (int d = lane; d < D_; d += 32) {
        float xv = xr[d];
        const float4* wr = (const float4*)(gw + (size_t)d * 8);
        float4 w0 = wr[0], w1 = wr[1];
        lg[0] += xv * w0.x; lg[1] += xv * w0.y; lg[2] += xv * w0.z; lg[3] += xv * w0.w;
        lg[4] += xv * w1.x; lg[5] += xv * w1.y; lg[6] += xv * w1.z; lg[7] += xv * w1.w;
    }
    #pragma unroll
    for (int o = 16; o > 0; o >>= 1) {
        #pragma unroll
        for (int e = 0; e < 8; e++) lg[e] += __shfl_xor_sync(0xffffffffu, lg[e], o);
    }
    if (lane == 0) {
        float p[8], mx = -1e30f;
        #pragma unroll
        for (int e = 0; e < 8; e++) { lg[e] += gb[e]; mx = fmaxf(mx, lg[e]); }
        float se = 0.f;
        #pragma unroll
        for (int e = 0; e < 8; e++) { p[e] = expf(lg[e] - mx); se += p[e]; }
        int i0 = 0;
        #pragma unroll
        for (int e = 1; e < 8; e++) if (p[e] > p[i0]) i0 = e;
        int i1 = (i0 == 0) ? 1 : 0;
        #pragma unroll
        for (int e = 0; e < 8; e++) if (e != i0 && p[e] > p[i1]) i1 = e;
        float v0 = p[i0] / se, v1 = p[i1] / se;
        float inv = 1.f / (v0 + v1 + 1e-6f);
        g_topi[t*2]   = i0; g_topi[t*2+1] = i1;
        g_topw[t*2]   = v0 * inv; g_topw[t*2+1] = v1 * inv;
        atomicAdd(&g_cnt[i0], 1);
        atomicAdd(&g_cnt[i1], 1);
    }
}

__global__ void offsets_kernel()
{
    if (threadIdx.x == 0) {
        int o = 0;
        for (int e = 0; e < E_; e++) {
            g_off[e] = o;
            o += (g_cnt[e] + 127) & ~127;
            g_cur[e] = 0;
        }
        g_off[E_] = o;
    }
}

__global__ void __launch_bounds__(256) place_gather_kernel()
{
    const int slot = blockIdx.x;
    const int t = slot >> 1;
    __shared__ int row_s;
    if (threadIdx.x == 0) {
        int e = g_topi[slot];
        int pos = atomicAdd(&g_cur[e], 1);
        int row = g_off[e] + pos;
        g_row[slot] = row;
        row_s = row;
    }
    __syncthreads();
    int row = row_s;
    ((uint2*)(g_xgh + (size_t)row * D_))[threadIdx.x] =
        ((const uint2*)(g_x2h + (size_t)t * D_))[threadIdx.x];
}

__global__ void __launch_bounds__(256) combine_kernel(float* __restrict__ out)
{
    const int t = blockIdx.x;
    const int r0 = g_row[2*t], r1 = g_row[2*t+1];
    const float w0 = g_topw[2*t], w1 = g_topw[2*t+1];
    const int c = threadIdx.x;
    float4 o  = ((float4*)(out + (size_t)t * D_))[c];
    float4 y0 = ((const float4*)(g_y + (size_t)r0 * D_))[c];
    float4 y1 = ((const float4*)(g_y + (size_t)r1 * D_))[c];
    o.x += w0 * y0.x + w1 * y1.x;
    o.y += w0 * y0.y + w1 * y1.y;
    o.z += w0 * y0.z + w1 * y1.z;
    o.w += w0 * y0.w + w1 * y1.w;
    ((float4*)(out + (size_t)t * D_))[c] = o;
}

// ---------------- launch ----------------
extern "C" void kernel_launch(void* const* d_in, const int* in_sizes, int n_in,
                              void* d_out, int out_size)
{
    const float* x    = (const float*)d_in[0];
    const float* wq1  = (const float*)d_in[1];
    const float* bq1  = (const float*)d_in[2];
    const float* wq2  = (const float*)d_in[3];
    const float* bq2  = (const float*)d_in[4];
    const float* wk1  = (const float*)d_in[5];
    const float* bk1  = (const float*)d_in[6];
    const float* wk2  = (const float*)d_in[7];
    const float* bk2  = (const float*)d_in[8];
    const float* wv1  = (const float*)d_in[9];
    const float* bv1  = (const float*)d_in[10];
    const float* wv2  = (const float*)d_in[11];
    const float* bv2  = (const float*)d_in[12];
    const float* wo   = (const float*)d_in[13];
    const float* bo   = (const float*)d_in[14];
    const float* ln1g = (const float*)d_in[15];
    const float* ln1b = (const float*)d_in[16];
    const float* ln2g = (const float*)d_in[17];
    const float* ln2b = (const float*)d_in[18];
    const float* gw   = (const float*)d_in[19];
    const float* gb   = (const float*)d_in[20];
    const float* ew1  = (const float*)d_in[21];
    const float* eb1  = (const float*)d_in[22];
    const float* ew2  = (const float*)d_in[23];
    const float* eb2  = (const float*)d_in[24];
    const float* ew3  = (const float*)d_in[25];
    const float* eb3  = (const float*)d_in[26];
    float* out = (float*)d_out;

    cudaFuncSetAttribute(mm_gated_kernel, cudaFuncAttributeMaxDynamicSharedMemorySize, SMEM_DUAL);
    cudaFuncSetAttribute(mm_moeh_kernel,  cudaFuncAttributeMaxDynamicSharedMemorySize, SMEM_DUAL);
    cudaFuncSetAttribute(mm_out_kernel,   cudaFuncAttributeMaxDynamicSharedMemorySize, SMEM_SINGLE);
    cudaFuncSetAttribute(mm_moey_kernel,  cudaFuncAttributeMaxDynamicSharedMemorySize, SMEM_SINGLE);

    __half *wd, *e1, *e3, *e2;
    float *qp, *kp, *vp;
    cudaGetSymbolAddress((void**)&wd, g_wd);
    cudaGetSymbolAddress((void**)&e1, g_e1);
    cudaGetSymbolAddress((void**)&e3, g_e3);
    cudaGetSymbolAddress((void**)&e2, g_e2);
    cudaGetSymbolAddress((void**)&qp, g_q);
    cudaGetSymbolAddress((void**)&kp, g_k);
    cudaGetSymbolAddress((void**)&vp, g_v);

    const size_t DD = (size_t)D_ * D_;
    const int N8_DD = (int)(DD / 8);            // 131072 -> 512 blocks
    const int N8_E  = (int)(8 * DD * 4 / 8);    // 4M -> 16384 blocks
    conv_kernel<<<N8_DD / 256, 256>>>(wq1, wd + 0 * DD, N8_DD);
    conv_kernel<<<N8_DD / 256, 256>>>(wq2, wd + 1 * DD, N8_DD);
    conv_kernel<<<N8_DD / 256, 256>>>(wk1, wd + 2 * DD, N8_DD);
    conv_kernel<<<N8_DD / 256, 256>>>(wk2, wd + 3 * DD, N8_DD);
    conv_kernel<<<N8_DD / 256, 256>>>(wv1, wd + 4 * DD, N8_DD);
    conv_kernel<<<N8_DD / 256, 256>>>(wv2, wd + 5 * DD, N8_DD);
    conv_kernel<<<N8_DD / 256, 256>>>(wo,  wd + 6 * DD, N8_DD);
    conv_kernel<<<N8_E / 256, 256>>>(ew1, e1, N8_E);
    conv_kernel<<<N8_E / 256, 256>>>(ew3, e3, N8_E);
    conv_kernel<<<N8_E / 256, 256>>>(ew2, e2, N8_E);

    dim3 gDD(TOK / 128, D_ / 128);   // 32 x 8

    ln_kernel<<<TOK, 256>>>(x, ln1g, ln1b);
    mm_gated_kernel<<<gDD, NTH, SMEM_DUAL>>>(wd + 0 * DD, wd + 1 * DD, bq1, bq2, qp, 1);
    mm_gated_kernel<<<gDD, NTH, SMEM_DUAL>>>(wd + 2 * DD, wd + 3 * DD, bk1, bk2, kp, 1);
    mm_gated_kernel<<<gDD, NTH, SMEM_DUAL>>>(wd + 4 * DD, wd + 5 * DD, bv1, bv2, vp, 0);
    kv_partial_kernel<<<dim3(32, 8), 256>>>();
    kv_reduce_kernel<<<(32 * DK_ * DK_ + 32 * DK_ + 255) / 256, 256>>>();
    attn_apply_kernel<<<dim3(32, S_ / 64), 256>>>();
    mm_out_kernel<<<gDD, NTH, SMEM_SINGLE>>>(wd + 6 * DD, bo, x, out);
    ln_kernel<<<TOK, 256>>>(out, ln2g, ln2b);
    zero_cnt_kernel<<<1, 32>>>();
    routing_kernel<<<TOK / 8, 256>>>(gw, gb);
    offsets_kernel<<<1, 1>>>();
    zero_xg_kernel<<<(int)(((size_t)CAP_ROWS * D_) / 2048), 256>>>();
    place_gather_kernel<<<TOK * 2, 256>>>();
    mm_moeh_kernel<<<dim3(CAP_ROWS / 128, F_ / 128), NTH, SMEM_DUAL>>>(eb1, eb3);
    mm_moey_kernel<<<dim3(CAP_ROWS / 128, D_ / 128), NTH, SMEM_SINGLE>>>(eb2);
    combine_kernel<<<TOK, 256>>>(out);
}

// round 6
// speedup vs baseline: 5.8183x; 1.1781x over previous
#include <cuda_runtime.h>
#include <cuda_fp16.h>
#include <math.h>
#include <stdint.h>

#define B_   2
#define S_   2048
#define D_   1024
#define H_   16
#define DK_  64
#define F_   4096
#define E_   8
#define TOK  (B_*S_)
#define CAP_ROWS (TOK*2 + E_*128)

#define KC   32               // k per chunk (halves)
#define SROW 40               // padded halves per A smem row (80B)
#define TILE_AB (128*SROW*2)  // 10240 bytes: A tile 128x32
#define TILE_BB (32*256)      // 8192 bytes: B tile 32(k) x 128(n), swizzled
#define STG_D  (TILE_AB + 2*TILE_BB)  // 26624
#define STG_S  (TILE_AB + 1*TILE_BB)  // 18432
#define NSTG 4
#define NTH  512

// ---------------- scratch ----------------
__device__ __align__(128) float  g_x2[TOK*D_];
__device__ __align__(128) __half g_x2h[TOK*D_];
__device__ __align__(128) float  g_q [TOK*D_];
__device__ __align__(128) float  g_k [TOK*D_];
__device__ __align__(128) float  g_v [TOK*D_];
__device__ __align__(128) __half g_ah[TOK*D_];
__device__ __align__(128) float  g_kvp[32*8*DK_*DK_];
__device__ __align__(128) float  g_kv [32*DK_*DK_];
__device__ __align__(128) float  g_ksp[32*8*DK_];
__device__ __align__(128) float  g_ks [32*DK_];
__device__ __align__(128) __half g_xgh[(size_t)CAP_ROWS*D_];
__device__ __align__(128) __half g_hh[(size_t)CAP_ROWS*F_];
__device__ __align__(128) float  g_y [(size_t)CAP_ROWS*D_];
__device__ __align__(128) __half g_wd[7*(size_t)D_*D_];     // fp16 copies, [K,N] layout
__device__ __align__(128) __half g_e1[8*(size_t)D_*F_];
__device__ __align__(128) __half g_e3[8*(size_t)D_*F_];
__device__ __align__(128) __half g_e2[8*(size_t)F_*D_];
__device__ int   g_cnt[E_];
__device__ int   g_off[E_+1];
__device__ int   g_cur[E_];
__device__ int   g_topi[TOK*2];
__device__ float g_topw[TOK*2];
__device__ int   g_row[TOK*2];

// ---------------- helpers ----------------
__device__ __forceinline__ uint32_t smem_u32(const void* p) {
    uint32_t a;
    asm("{ .reg .u64 t; cvta.to.shared.u64 t, %1; cvt.u32.u64 %0, t; }" : "=r"(a) : "l"(p));
    return a;
}
__device__ __forceinline__ float silu_gate(float a, float c) {
    return a / (1.f + expf(-a)) * c;
}
__device__ __forceinline__ float phi1(float x) { return x > 0.f ? x + 1.f : expf(x); }

__device__ __forceinline__ void cp16(uint32_t s, const void* g) {
    asm volatile("cp.async.cg.shared.global [%0], [%1], 16;" :: "r"(s), "l"(g) : "memory");
}

#define LDSM4(r, addr) \
    asm volatile("ldmatrix.sync.aligned.m8n8.x4.shared.b16 {%0,%1,%2,%3}, [%4];" \
        : "=r"((r)[0]), "=r"((r)[1]), "=r"((r)[2]), "=r"((r)[3]) : "r"(addr))
#define LDSM2T(r, addr) \
    asm volatile("ldmatrix.sync.aligned.m8n8.x2.trans.shared.b16 {%0,%1}, [%2];" \
        : "=r"((r)[0]), "=r"((r)[1]) : "r"(addr))
#define MMA_F16(c, a, b) \
    asm volatile("mma.sync.aligned.m16n8k16.row.col.f32.f16.f16.f32 " \
        "{%0,%1,%2,%3}, {%4,%5,%6,%7}, {%8,%9}, {%0,%1,%2,%3};" \
        : "+f"((c)[0]), "+f"((c)[1]), "+f"((c)[2]), "+f"((c)[3]) \
        : "r"((a)[0]), "r"((a)[1]), "r"((a)[2]), "r"((a)[3]), "r"((b)[0]), "r"((b)[1]))

// ---------------- mma.sync GEMM core ----------------
// A [M x K] row-major half (padded smem rows, regular ldmatrix).
// B [K x N] row-major half, K-major swizzled smem tile + ldmatrix.x2.trans.
template<int DUAL>
__device__ __forceinline__ void ld_chunk(
    const __half* A, int lda, const __half* B0, const __half* B1, int ldb,
    int k0, uint32_t st, int tid)
{
    const int r = tid >> 2;
    const int c = (tid & 3) * 8;
    cp16(st + (uint32_t)(r * SROW + c) * 2, A + (size_t)r * lda + k0 + c);
    const int bk = tid >> 4;
    const int bg = tid & 15;
    const uint32_t bso = (uint32_t)bk * 256 + (uint32_t)((bg ^ (bk & 7)) << 4);
    const size_t go = (size_t)(k0 + bk) * ldb + bg * 8;
    cp16(st + TILE_AB + bso, B0 + go);
    if (DUAL) cp16(st + TILE_AB + TILE_BB + bso, B1 + go);
}

template<int DUAL>
__device__ __forceinline__ void compute_chunk(
    uint32_t st, float (&acc0)[2][4][4], float (&acc1)[2][4][4],
    int wm, int wn, int lane)
{
    const uint32_t aoff = (uint32_t)(((lane & 7) + ((lane >> 3) & 1) * 8) * SROW + (lane >> 4) * 8) * 2;
    const uint32_t stB0 = st + TILE_AB;
    const uint32_t stB1 = st + TILE_AB + TILE_BB;
    #pragma unroll
    for (int ks = 0; ks < 2; ks++) {
        uint32_t a[2][4];
        #pragma unroll
        for (int mt = 0; mt < 2; mt++) {
            uint32_t addr = st + (uint32_t)((wm * 32 + mt * 16) * SROW + ks * 16) * 2 + aoff;
            LDSM4(a[mt], addr);
        }
        const int kk = ks * 16 + (lane & 15);
        const uint32_t brow = (uint32_t)kk * 256;
        const uint32_t kx = (uint32_t)(kk & 7) << 4;
        #pragma unroll
        for (int nt = 0; nt < 4; nt++) {
            const uint32_t gy = ((uint32_t)(wn * 4 + nt) << 4) ^ kx;
            uint32_t b[2];
            LDSM2T(b, stB0 + brow + gy);
            MMA_F16(acc0[0][nt], a[0], b);
            MMA_F16(acc0[1][nt], a[1], b);
        }
        if (DUAL) {
            #pragma unroll
            for (int nt = 0; nt < 4; nt++) {
                const uint32_t gy = ((uint32_t)(wn * 4 + nt) << 4) ^ kx;
                uint32_t b[2];
                LDSM2T(b, stB1 + brow + gy);
                MMA_F16(acc1[0][nt], a[0], b);
                MMA_F16(acc1[1][nt], a[1], b);
            }
        }
    }
}

// 4-stage pipeline, one __syncthreads per chunk, always-commit for valid tail.
template<int DUAL>
__device__ __forceinline__ void mma_mainloop(
    const __half* A, int lda, const __half* B0, const __half* B1, int ldb,
    int K, uint32_t sm, float (&acc0)[2][4][4], float (&acc1)[2][4][4])
{
    const int tid = threadIdx.x;
    const int lane = tid & 31, wid = tid >> 5;
    const int wm = wid & 3, wn = wid >> 2;
    const uint32_t STAGE = DUAL ? STG_D : STG_S;
    const int NC = K / KC;
    #pragma unroll
    for (int p = 0; p < NSTG - 1; p++) {
        ld_chunk<DUAL>(A, lda, B0, B1, ldb, p * KC, sm + (uint32_t)p * STAGE, tid);
        asm volatile("cp.async.commit_group;" ::: "memory");
    }
    for (int k = 0; k < NC; k++) {
        asm volatile("cp.async.wait_group 2;" ::: "memory");
        __syncthreads();
        if (k + NSTG - 1 < NC)
            ld_chunk<DUAL>(A, lda, B0, B1, ldb, (k + NSTG - 1) * KC,
                           sm + (uint32_t)((k + NSTG - 1) & (NSTG - 1)) * STAGE, tid);
        asm volatile("cp.async.commit_group;" ::: "memory");
        compute_chunk<DUAL>(sm + (uint32_t)(k & (NSTG - 1)) * STAGE, acc0, acc1, wm, wn, lane);
    }
}

// ---------------- GEMM kernels ----------------
#define SMEM_DUAL   (NSTG*STG_D)   // 106496
#define SMEM_SINGLE (NSTG*STG_S)   // 73728

struct GatedArgs {
    const __half* w1[3];
    const __half* w2[3];
    const float*  b1[3];
    const float*  b2[3];
    float*        C [3];
};

// z in {0,1,2}: q(phi), k(phi), v(no phi)
__global__ void __launch_bounds__(NTH, 1) mm_gated_kernel(GatedArgs ga)
{
    extern __shared__ __align__(128) char smem[];
    uint32_t sm = smem_u32(smem);
    const int z = blockIdx.z;
    const int bm0 = blockIdx.x * 128, bn0 = blockIdx.y * 128;
    float acc0[2][4][4] = {}, acc1[2][4][4] = {};
    mma_mainloop<1>(g_x2h + (size_t)bm0 * D_, D_,
                    ga.w1[z] + bn0, ga.w2[z] + bn0, D_,
                    D_, sm, acc0, acc1);
    const float* bias1 = ga.b1[z];
    const float* bias2 = ga.b2[z];
    float* C = ga.C[z];
    const int applyPhi = (z != 2);
    const int lane = threadIdx.x & 31, wid = threadIdx.x >> 5;
    const int wm = wid & 3, wn = wid >> 2;
    const int quad = lane >> 2, tq = lane & 3;
    #pragma unroll
    for (int mt = 0; mt < 2; mt++) {
        #pragma unroll
        for (int nt = 0; nt < 4; nt++) {
            const int col = bn0 + wn * 32 + nt * 8 + tq * 2;
            const int r0 = bm0 + wm * 32 + mt * 16 + quad;
            float2 bb1 = *(const float2*)(bias1 + col);
            float2 bb2 = *(const float2*)(bias2 + col);
            float2 v;
            v.x = silu_gate(acc0[mt][nt][0] + bb1.x, acc1[mt][nt][0] + bb2.x);
            v.y = silu_gate(acc0[mt][nt][1] + bb1.y, acc1[mt][nt][1] + bb2.y);
            if (applyPhi) { v.x = phi1(v.x); v.y = phi1(v.y); }
            *(float2*)(C + (size_t)r0 * D_ + col) = v;
            v.x = silu_gate(acc0[mt][nt][2] + bb1.x, acc1[mt][nt][2] + bb2.x);
            v.y = silu_gate(acc0[mt][nt][3] + bb1.y, acc1[mt][nt][3] + bb2.y);
            if (applyPhi) { v.x = phi1(v.x); v.y = phi1(v.y); }
            *(float2*)(C + (size_t)(r0 + 8) * D_ + col) = v;
        }
    }
}

__global__ void __launch_bounds__(NTH, 1) mm_out_kernel(
    const __half* __restrict__ w, const float* __restrict__ bias,
    const float* __restrict__ res, float* __restrict__ C)
{
    extern __shared__ __align__(128) char smem[];
    uint32_t sm = smem_u32(smem);
    const int bm0 = blockIdx.x * 128, bn0 = blockIdx.y * 128;
    float acc0[2][4][4] = {}, acc1[2][4][4];
    mma_mainloop<0>(g_ah + (size_t)bm0 * D_, D_, w + bn0, (const __half*)0, D_,
                    D_, sm, acc0, acc1);
    const int lane = threadIdx.x & 31, wid = threadIdx.x >> 5;
    const int wm = wid & 3, wn = wid >> 2;
    const int quad = lane >> 2, tq = lane & 3;
    #pragma unroll
    for (int mt = 0; mt < 2; mt++) {
        #pragma unroll
        for (int nt = 0; nt < 4; nt++) {
            const int col = bn0 + wn * 32 + nt * 8 + tq * 2;
            const int r0 = bm0 + wm * 32 + mt * 16 + quad;
            float2 bb = *(const float2*)(bias + col);
            float2 rr0 = *(const float2*)(res + (size_t)r0 * D_ + col);
            float2 rr1 = *(const float2*)(res + (size_t)(r0 + 8) * D_ + col);
            float2 v;
            v.x = acc0[mt][nt][0] + bb.x + rr0.x;
            v.y = acc0[mt][nt][1] + bb.y + rr0.y;
            *(float2*)(C + (size_t)r0 * D_ + col) = v;
            v.x = acc0[mt][nt][2] + bb.x + rr1.x;
            v.y = acc0[mt][nt][3] + bb.y + rr1.y;
            *(float2*)(C + (size_t)(r0 + 8) * D_ + col) = v;
        }
    }
}

__global__ void __launch_bounds__(NTH, 1) mm_moeh_kernel(
    const float* __restrict__ eb1, const float* __restrict__ eb3)
{
    const int bm0 = blockIdx.x * 128;
    if (bm0 >= g_off[E_]) return;
    int e = 0;
    #pragma unroll
    for (int i = 0; i < E_; i++) if (bm0 >= g_off[i + 1]) e = i + 1;
    extern __shared__ __align__(128) char smem[];
    uint32_t sm = smem_u32(smem);
    const int bn0 = blockIdx.y * 128;
    const size_t wb = (size_t)e * D_ * F_ + bn0;
    float acc0[2][4][4] = {}, acc1[2][4][4] = {};
    mma_mainloop<1>(g_xgh + (size_t)bm0 * D_, D_, g_e1 + wb, g_e3 + wb, F_,
                    D_, sm, acc0, acc1);
    const int lane = threadIdx.x & 31, wid = threadIdx.x >> 5;
    const int wm = wid & 3, wn = wid >> 2;
    const int quad = lane >> 2, tq = lane & 3;
    const float* b1 = eb1 + (size_t)e * F_;
    const float* b3 = eb3 + (size_t)e * F_;
    #pragma unroll
    for (int mt = 0; mt < 2; mt++) {
        #pragma unroll
        for (int nt = 0; nt < 4; nt++) {
            const int col = bn0 + wn * 32 + nt * 8 + tq * 2;
            const int r0 = bm0 + wm * 32 + mt * 16 + quad;
            float2 bb1 = *(const float2*)(b1 + col);
            float2 bb3 = *(const float2*)(b3 + col);
            float v0 = silu_gate(acc0[mt][nt][0] + bb1.x, acc1[mt][nt][0] + bb3.x);
            float v1 = silu_gate(acc0[mt][nt][1] + bb1.y, acc1[mt][nt][1] + bb3.y);
            *(__half2*)(g_hh + (size_t)r0 * F_ + col) = __floats2half2_rn(v0, v1);
            v0 = silu_gate(acc0[mt][nt][2] + bb1.x, acc1[mt][nt][2] + bb3.x);
            v1 = silu_gate(acc0[mt][nt][3] + bb1.y, acc1[mt][nt][3] + bb3.y);
            *(__half2*)(g_hh + (size_t)(r0 + 8) * F_ + col) = __floats2half2_rn(v0, v1);
        }
    }
}

__global__ void __launch_bounds__(NTH, 1) mm_moey_kernel(const float* __restrict__ eb2)
{
    const int bm0 = blockIdx.x * 128;
    if (bm0 >= g_off[E_]) return;
    int e = 0;
    #pragma unroll
    for (int i = 0; i < E_; i++) if (bm0 >= g_off[i + 1]) e = i + 1;
    extern __shared__ __align__(128) char smem[];
    uint32_t sm = smem_u32(smem);
    const int bn0 = blockIdx.y * 128;
    const size_t wb = (size_t)e * F_ * D_ + bn0;
    float acc0[2][4][4] = {}, acc1[2][4][4];
    mma_mainloop<0>(g_hh + (size_t)bm0 * F_, F_, g_e2 + wb, (const __half*)0, D_,
                    F_, sm, acc0, acc1);
    const int lane = threadIdx.x & 31, wid = threadIdx.x >> 5;
    const int wm = wid & 3, wn = wid >> 2;
    const int quad = lane >> 2, tq = lane & 3;
    const float* b2 = eb2 + (size_t)e * D_;
    #pragma unroll
    for (int mt = 0; mt < 2; mt++) {
        #pragma unroll
        for (int nt = 0; nt < 4; nt++) {
            const int col = bn0 + wn * 32 + nt * 8 + tq * 2;
            const int r0 = bm0 + wm * 32 + mt * 16 + quad;
            float2 bb = *(const float2*)(b2 + col);
            float2 v;
            v.x = acc0[mt][nt][0] + bb.x;
            v.y = acc0[mt][nt][1] + bb.y;
            *(float2*)(g_y + (size_t)r0 * D_ + col) = v;
            v.x = acc0[mt][nt][2] + bb.x;
            v.y = acc0[mt][nt][3] + bb.y;
            *(float2*)(g_y + (size_t)(r0 + 8) * D_ + col) = v;
        }
    }
}

// ---------------- conversion: streaming fp32 -> fp16, 16 elems/thread ----------------
__device__ __forceinline__ void conv16(const float* S, __half* Dst, int i)
{
    #pragma unroll
    for (int h = 0; h < 2; h++) {
        float4 a = ((const float4*)S)[4 * i + 2 * h];
        float4 b = ((const float4*)S)[4 * i + 2 * h + 1];
        __half2 h0 = __floats2half2_rn(a.x, a.y);
        __half2 h1 = __floats2half2_rn(a.z, a.w);
        __half2 h2 = __floats2half2_rn(b.x, b.y);
        __half2 h3 = __floats2half2_rn(b.z, b.w);
        uint4 o;
        o.x = *(uint32_t*)&h0; o.y = *(uint32_t*)&h1;
        o.z = *(uint32_t*)&h2; o.w = *(uint32_t*)&h3;
        ((uint4*)Dst)[2 * i + h] = o;
    }
}

__global__ void __launch_bounds__(256) conv_kernel(
    const float* __restrict__ S, __half* __restrict__ Dst, int n16)
{
    int i = blockIdx.x * 256 + threadIdx.x;
    if (i < n16) conv16(S, Dst, i);
}

struct Ptr7 { const float* p[7]; };
__global__ void __launch_bounds__(256) conv7_kernel(Ptr7 src, __half* dst)
{
    const int m = blockIdx.y;
    const int n16 = (int)((size_t)D_ * D_ / 16);
    int i = blockIdx.x * 256 + threadIdx.x;
    if (i < n16) conv16(src.p[m], dst + (size_t)m * D_ * D_, i);
}

// ---------------- non-GEMM kernels ----------------
__global__ void __launch_bounds__(256) ln_kernel(
    const float* __restrict__ x, const float* __restrict__ g, const float* __restrict__ b)
{
    __shared__ float rs[256], rq[256];
    const int t = blockIdx.x, tid = threadIdx.x;
    float4 v = ((const float4*)(x + (size_t)t * D_))[tid];
    rs[tid] = v.x + v.y + v.z + v.w;
    rq[tid] = v.x * v.x + v.y * v.y + v.z * v.z + v.w * v.w;
    __syncthreads();
    for (int o = 128; o > 0; o >>= 1) {
        if (tid < o) { rs[tid] += rs[tid + o]; rq[tid] += rq[tid + o]; }
        __syncthreads();
    }
    float mean = rs[0] * (1.f / D_);
    float var  = rq[0] * (1.f / D_) - mean * mean;
    float inv  = rsqrtf(var + 1e-5f);
    float4 gg = ((const float4*)g)[tid];
    float4 bb = ((const float4*)b)[tid];
    float4 o4;
    o4.x = (v.x - mean) * inv * gg.x + bb.x;
    o4.y = (v.y - mean) * inv * gg.y + bb.y;
    o4.z = (v.z - mean) * inv * gg.z + bb.z;
    o4.w = (v.w - mean) * inv * gg.w + bb.w;
    ((float4*)(g_x2 + (size_t)t * D_))[tid] = o4;
    size_t ob = (size_t)t * D_ + tid * 4;
    ((__half2*)(g_x2h + ob))[0] = __floats2half2_rn(o4.x, o4.y);
    ((__half2*)(g_x2h + ob))[1] = __floats2half2_rn(o4.z, o4.w);
}

// 8 s-rows per barrier round
__global__ void __launch_bounds__(256) kv_partial_kernel()
{
    __shared__ float pk[8*DK_], pv[8*DK_];
    const int bh = blockIdx.x, c = blockIdx.y;
    const int b = bh >> 4, h = bh & 15;
    const int tid = threadIdx.x;
    const int d = tid >> 2, eg = tid & 3;
    const int lr = tid >> 5;           // 0..7 row for loading
    const int lc = (tid & 31) * 2;     // 0..62
    float acc[16];
    #pragma unroll
    for (int j = 0; j < 16; j++) acc[j] = 0.f;
    float ks = 0.f;
    for (int s0 = c * 256; s0 < c * 256 + 256; s0 += 8) {
        size_t base = ((size_t)(b * S_ + s0 + lr)) * D_ + h * DK_ + lc;
        *(float2*)&pk[lr * DK_ + lc] = *(const float2*)&g_k[base];
        *(float2*)&pv[lr * DK_ + lc] = *(const float2*)&g_v[base];
        __syncthreads();
        #pragma unroll
        for (int i = 0; i < 8; i++) {
            float kd = pk[i * DK_ + d];
            #pragma unroll
            for (int j = 0; j < 16; j++) acc[j] += kd * pv[i * DK_ + eg + 4 * j];
            if (eg == 0) ks += kd;
        }
        __syncthreads();
    }
    size_t ob = ((size_t)(bh * 8 + c)) * DK_ * DK_;
    #pragma unroll
    for (int j = 0; j < 16; j++) g_kvp[ob + d * DK_ + eg + 4 * j] = acc[j];
    if (eg == 0) g_ksp[(bh * 8 + c) * DK_ + d] = ks;
}

__global__ void kv_reduce_kernel()
{
    int i = blockIdx.x * 256 + threadIdx.x;
    if (i < 32 * DK_ * DK_) {
        int bh = i >> 12, r = i & 4095;
        float s = 0.f;
        #pragma unroll
        for (int c = 0; c < 8; c++) s += g_kvp[((size_t)(bh * 8 + c)) * 4096 + r];
        g_kv[i] = s;
    }
    int j = i - 32 * DK_ * DK_;
    if (j >= 0 && j < 32 * DK_) {
        int bh = j >> 6, d = j & 63;
        float s = 0.f;
        #pragma unroll
        for (int c = 0; c < 8; c++) s += g_ksp[(bh * 8 + c) * DK_ + d];
        g_ks[j] = s;
    }
}

// single barrier; all 64 q-rows preloaded
__global__ void __launch_bounds__(256) attn_apply_kernel()
{
    __shared__ float kvs[DK_*DK_];
    __shared__ float kss[DK_];
    __shared__ float qs[64*DK_];
    const int bh = blockIdx.x;
    const int b = bh >> 4, h = bh & 15;
    const int tid = threadIdx.x;
    for (int i = tid; i < DK_ * DK_; i += 256) kvs[i] = g_kv[(size_t)bh * DK_ * DK_ + i];
    if (tid < DK_) kss[tid] = g_ks[bh * DK_ + tid];
    const int sbase = blockIdx.y * 64;
    #pragma unroll
    for (int i = 0; i < 16; i++) {
        int idx = tid + 256 * i;
        int sr = idx >> 6, dd = idx & 63;
        qs[idx] = g_q[((size_t)(b * S_ + sbase + sr)) * D_ + h * DK_ + dd];
    }
    __syncthreads();
    const int sl = tid >> 6, e = tid & 63;
    #pragma unroll 4
    for (int pass = 0; pass < 16; pass++) {
        const int srow = pass * 4 + sl;
        float acc = 0.f, qk = 0.f;
        #pragma unroll
        for (int d = 0; d < DK_; d++) {
            float qd = qs[srow * DK_ + d];
            acc += qd * kvs[d * DK_ + e];
            qk  += qd * kss[d];
        }
        g_ah[((size_t)(b * S_ + sbase + srow)) * D_ + h * DK_ + e] = __float2half(acc / (qk + 1e-6f));
    }
}

__global__ void zero_cnt_kernel() { if (threadIdx.x < E_) g_cnt[threadIdx.x] = 0; }

__global__ void zero_xg_kernel()
{
    size_t i = (size_t)blockIdx.x * 256 + threadIdx.x;
    ((uint4*)g_xgh)[i] = make_uint4(0u, 0u, 0u, 0u);
}

__global__ void __launch_bounds__(256) routing_kernel(
    const float* __restrict__ gw, const float* __restrict__ gb)
{
    const int lane = threadIdx.x & 31;
    const int warp = threadIdx.x >> 5;
    const int t = blockIdx.x * 8 + warp;
    const float* xr = g_x2 + (size_t)t * D_;
    float lg[8];
    #pragma unroll
    for (int e = 0; e < 8; e++) lg[e] = 0.f;
    for (int d = lane; d < D_; d += 32) {
        float xv = xr[d];
        const float4* wr = (const float4*)(gw + (size_t)d * 8);
        float4 w0 = wr[0], w1 = wr[1];
        lg[0] += xv * w0.x; lg[1] += xv * w0.y; lg[2] += xv * w0.z; lg[3] += xv * w0.w;
        lg[4] += xv * w1.x; lg[5] += xv * w1.y; lg[6] += xv * w1.z; lg[7] += xv * w1.w;
    }
    #pragma unroll
    for (int o = 16; o > 0; o >>= 1) {
        #pragma unroll
        for (int e = 0; e < 8; e++) lg[e] += __shfl_xor_sync(0xffffffffu, lg[e], o);
    }
    if (lane == 0) {
        float p[8], mx = -1e30f;
        #pragma unroll
        for (int e = 0; e < 8; e++) { lg[e] += gb[e]; mx = fmaxf(mx, lg[e]); }
        float se = 0.f;
        #pragma unroll
        for (int e = 0; e < 8; e++) { p[e] = expf(lg[e] - mx); se += p[e]; }
        int i0 = 0;
        #pragma unroll
        for (int e = 1; e < 8; e++) if (p[e] > p[i0]) i0 = e;
        int i1 = (i0 == 0) ? 1 : 0;
        #pragma unroll
        for (int e = 0; e < 8; e++) if (e != i0 && p[e] > p[i1]) i1 = e;
        float v0 = p[i0] / se, v1 = p[i1] / se;
        float inv = 1.f / (v0 + v1 + 1e-6f);
        g_topi[t*2]   = i0; g_topi[t*2+1] = i1;
        g_topw[t*2]   = v0 * inv; g_topw[t*2+1] = v1 * inv;
        atomicAdd(&g_cnt[i0], 1);
        atomicAdd(&g_cnt[i1], 1);
    }
}

__global__ void offsets_kernel()
{
    if (threadIdx.x == 0) {
        int o = 0;
        for (int e = 0; e < E_; e++) {
            g_off[e] = o;
            o += (g_cnt[e] + 127) & ~127;
            g_cur[e] = 0;
        }
        g_off[E_] = o;
    }
}

__global__ void __launch_bounds__(256) place_gather_kernel()
{
    const int slot = blockIdx.x;
    const int t = slot >> 1;
    __shared__ int row_s;
    if (threadIdx.x == 0) {
        int e = g_topi[slot];
        int pos = atomicAdd(&g_cur[e], 1);
        int row = g_off[e] + pos;
        g_row[slot] = row;
        row_s = row;
    }
    __syncthreads();
    int row = row_s;
    ((uint2*)(g_xgh + (size_t)row * D_))[threadIdx.x] =
        ((const uint2*)(g_x2h + (size_t)t * D_))[threadIdx.x];
}

__global__ void __launch_bounds__(256) combine_kernel(float* __restrict__ out)
{
    const int t = blockIdx.x;
    const int r0 = g_row[2*t], r1 = g_row[2*t+1];
    const float w0 = g_topw[2*t], w1 = g_topw[2*t+1];
    const int c = threadIdx.x;
    float4 o  = ((float4*)(out + (size_t)t * D_))[c];
    float4 y0 = ((const float4*)(g_y + (size_t)r0 * D_))[c];
    float4 y1 = ((const float4*)(g_y + (size_t)r1 * D_))[c];
    o.x += w0 * y0.x + w1 * y1.x;
    o.y += w0 * y0.y + w1 * y1.y;
    o.z += w0 * y0.z + w1 * y1.z;
    o.w += w0 * y0.w + w1 * y1.w;
    ((float4*)(out + (size_t)t * D_))[c] = o;
}

// ---------------- launch ----------------
extern "C" void kernel_launch(void* const* d_in, const int* in_sizes, int n_in,
                              void* d_out, int out_size)
{
    const float* x    = (const float*)d_in[0];
    const float* wq1  = (const float*)d_in[1];
    const float* bq1  = (const float*)d_in[2];
    const float* wq2  = (const float*)d_in[3];
    const float* bq2  = (const float*)d_in[4];
    const float* wk1  = (const float*)d_in[5];
    const float* bk1  = (const float*)d_in[6];
    const float* wk2  = (const float*)d_in[7];
    const float* bk2  = (const float*)d_in[8];
    const float* wv1  = (const float*)d_in[9];
    const float* bv1  = (const float*)d_in[10];
    const float* wv2  = (const float*)d_in[11];
    const float* bv2  = (const float*)d_in[12];
    const float* wo   = (const float*)d_in[13];
    const float* bo   = (const float*)d_in[14];
    const float* ln1g = (const float*)d_in[15];
    const float* ln1b = (const float*)d_in[16];
    const float* ln2g = (const float*)d_in[17];
    const float* ln2b = (const float*)d_in[18];
    const float* gw   = (const float*)d_in[19];
    const float* gb   = (const float*)d_in[20];
    const float* ew1  = (const float*)d_in[21];
    const float* eb1  = (const float*)d_in[22];
    const float* ew2  = (const float*)d_in[23];
    const float* eb2  = (const float*)d_in[24];
    const float* ew3  = (const float*)d_in[25];
    const float* eb3  = (const float*)d_in[26];
    float* out = (float*)d_out;

    cudaFuncSetAttribute(mm_gated_kernel, cudaFuncAttributeMaxDynamicSharedMemorySize, SMEM_DUAL);
    cudaFuncSetAttribute(mm_moeh_kernel,  cudaFuncAttributeMaxDynamicSharedMemorySize, SMEM_DUAL);
    cudaFuncSetAttribute(mm_out_kernel,   cudaFuncAttributeMaxDynamicSharedMemorySize, SMEM_SINGLE);
    cudaFuncSetAttribute(mm_moey_kernel,  cudaFuncAttributeMaxDynamicSharedMemorySize, SMEM_SINGLE);

    __half *wd, *e1, *e3, *e2;
    float *qp, *kp, *vp;
    cudaGetSymbolAddress((void**)&wd, g_wd);
    cudaGetSymbolAddress((void**)&e1, g_e1);
    cudaGetSymbolAddress((void**)&e3, g_e3);
    cudaGetSymbolAddress((void**)&e2, g_e2);
    cudaGetSymbolAddress((void**)&qp, g_q);
    cudaGetSymbolAddress((void**)&kp, g_k);
    cudaGetSymbolAddress((void**)&vp, g_v);

    const size_t DD = (size_t)D_ * D_;
    const int N16_DD = (int)(DD / 16);          // 65536 -> 256 blocks
    const int N16_E  = (int)(8 * DD * 4 / 16);  // 2M -> 8192 blocks

    Ptr7 p7;
    p7.p[0] = wq1; p7.p[1] = wq2; p7.p[2] = wk1; p7.p[3] = wk2;
    p7.p[4] = wv1; p7.p[5] = wv2; p7.p[6] = wo;
    conv7_kernel<<<dim3(N16_DD / 256, 7), 256>>>(p7, wd);
    conv_kernel<<<N16_E / 256, 256>>>(ew1, e1, N16_E);
    conv_kernel<<<N16_E / 256, 256>>>(ew3, e3, N16_E);
    conv_kernel<<<N16_E / 256, 256>>>(ew2, e2, N16_E);

    dim3 gDD(TOK / 128, D_ / 128);   // 32 x 8

    ln_kernel<<<TOK, 256>>>(x, ln1g, ln1b);

    GatedArgs ga;
    ga.w1[0] = wd + 0 * DD; ga.w2[0] = wd + 1 * DD; ga.b1[0] = bq1; ga.b2[0] = bq2; ga.C[0] = qp;
    ga.w1[1] = wd + 2 * DD; ga.w2[1] = wd + 3 * DD; ga.b1[1] = bk1; ga.b2[1] = bk2; ga.C[1] = kp;
    ga.w1[2] = wd + 4 * DD; ga.w2[2] = wd + 5 * DD; ga.b1[2] = bv1; ga.b2[2] = bv2; ga.C[2] = vp;
    mm_gated_kernel<<<dim3(TOK / 128, D_ / 128, 3), NTH, SMEM_DUAL>>>(ga);

    kv_partial_kernel<<<dim3(32, 8), 256>>>();
    kv_reduce_kernel<<<(32 * DK_ * DK_ + 32 * DK_ + 255) / 256, 256>>>();
    attn_apply_kernel<<<dim3(32, S_ / 64), 256>>>();
    mm_out_kernel<<<gDD, NTH, SMEM_SINGLE>>>(wd + 6 * DD, bo, x, out);
    ln_kernel<<<TOK, 256>>>(out, ln2g, ln2b);
    zero_cnt_kernel<<<1, 32>>>();
    routing_kernel<<<TOK / 8, 256>>>(gw, gb);
    offsets_kernel<<<1, 1>>>();
    zero_xg_kernel<<<(int)(((size_t)CAP_ROWS * D_) / 2048), 256>>>();
    place_gather_kernel<<<TOK * 2, 256>>>();
    mm_moeh_kernel<<<dim3(CAP_ROWS / 128, F_ / 128), NTH, SMEM_DUAL>>>(eb1, eb3);
    mm_moey_kernel<<<dim3(CAP_ROWS / 128, D_ / 128), NTH, SMEM_SINGLE>>>(eb2);
    combine_kernel<<<TOK, 256>>>(out);
}